// round 14
// baseline (speedup 1.0000x reference)
#include <cuda_runtime.h>
#include <cuda_bf16.h>
#include <cuda_fp16.h>
#include <cstdint>
#include <math.h>

typedef __nv_bfloat16 bf16;

#define TT    2048
#define KDIM  2048
#define DH    128
#define NREDC 1152
#define MROWS 8192
#define NBH   16
#define SCALE 0.08838834764831845f   // 1/sqrt(128)

// ---------------- device scratch ----------------
__device__ bf16   g_xhi[(size_t)MROWS*KDIM];
__device__ bf16   g_xlo[(size_t)MROWS*KDIM];
__device__ __half g_x16[(size_t)MROWS*KDIM];     // x single fp16 (V-GEMM)
__device__ bf16   g_whi[(size_t)NREDC*KDIM];
__device__ bf16   g_wlo[(size_t)NREDC*KDIM];
__device__ __half g_wv16[(size_t)512*KDIM];      // V weights fp16 (rows n-640)
__device__ float  g_bred[NREDC];
__device__ bf16   g_qhi[(size_t)MROWS*DH];
__device__ bf16   g_qlo[(size_t)MROWS*DH];
__device__ bf16   g_khi[(size_t)NBH*TT*DH];
__device__ bf16   g_klo[(size_t)NBH*TT*DH];
__device__ __half g_v16[(size_t)NBH*TT*DH];      // V [bh][t][d], single fp16

// ---------------- helpers ----------------
__device__ __forceinline__ void split2(float v, bf16& h, bf16& l) {
    h = __float2bfloat16(v);
    l = __float2bfloat16(v - __bfloat162float(h));
}
__device__ __forceinline__ unsigned h2u(__half2 h) {
    return *reinterpret_cast<unsigned*>(&h);
}
__device__ __forceinline__ void cp16(void* sp, const void* gp) {
    unsigned s = (unsigned)__cvta_generic_to_shared(sp);
    asm volatile("cp.async.cg.shared.global [%0], [%1], 16;\n" :: "r"(s), "l"(gp));
}
__device__ __forceinline__ void cp16s(unsigned s, const void* gp) {
    asm volatile("cp.async.cg.shared.global [%0], [%1], 16;\n" :: "r"(s), "l"(gp));
}
#define CP_COMMIT() asm volatile("cp.async.commit_group;\n")
#define CP_WAIT(n)  asm volatile("cp.async.wait_group %0;\n" :: "n"(n))

// swizzled element offset inside an Nx32 16-bit tile (64B rows, 16B chunks)
#define SWZ(r, c) (((r) << 5) + ((((c) ^ (((r) >> 1) & 3))) << 3))

#define LDSM4(R, addr) \
    asm volatile("ldmatrix.sync.aligned.m8n8.x4.shared.b16 {%0,%1,%2,%3}, [%4];" \
        : "=r"((R)[0]), "=r"((R)[1]), "=r"((R)[2]), "=r"((R)[3]) : "r"(addr))

#define LDSM4T(R, addr) \
    asm volatile("ldmatrix.sync.aligned.m8n8.x4.trans.shared.b16 {%0,%1,%2,%3}, [%4];" \
        : "=r"((R)[0]), "=r"((R)[1]), "=r"((R)[2]), "=r"((R)[3]) : "r"(addr))

#define MMA_BF16(C, A, b0, b1) \
    asm volatile("mma.sync.aligned.m16n8k16.row.col.f32.bf16.bf16.f32 " \
        "{%0,%1,%2,%3},{%4,%5,%6,%7},{%8,%9},{%0,%1,%2,%3};" \
        : "+f"((C)[0]), "+f"((C)[1]), "+f"((C)[2]), "+f"((C)[3]) \
        : "r"((A)[0]), "r"((A)[1]), "r"((A)[2]), "r"((A)[3]), "r"(b0), "r"(b1))

#define MMA_F16(C, A, b0, b1) \
    asm volatile("mma.sync.aligned.m16n8k16.row.col.f32.f16.f16.f32 " \
        "{%0,%1,%2,%3},{%4,%5,%6,%7},{%8,%9},{%0,%1,%2,%3};" \
        : "+f"((C)[0]), "+f"((C)[1]), "+f"((C)[2]), "+f"((C)[3]) \
        : "r"((A)[0]), "r"((A)[1]), "r"((A)[2]), "r"((A)[3]), "r"(b0), "r"(b1))

// ---------------- prep ----------------
__global__ void prep_x(const float* __restrict__ x) {
    size_t i = ((size_t)blockIdx.x * 256 + threadIdx.x) * 4;
    float4 a = *(const float4*)(x + i);
    float arr[4] = {a.x, a.y, a.z, a.w};
#pragma unroll
    for (int j = 0; j < 4; j++) {
        bf16 h, l; split2(arr[j], h, l);
        g_xhi[i + j] = h;  g_xlo[i + j] = l;
        g_x16[i + j] = __float2half(arr[j]);
    }
}

__global__ void prep_w(const float* __restrict__ W, const float* __restrict__ b) {
    int idx = blockIdx.x * 256 + threadIdx.x;
    int n = idx >> 11, c = idx & 2047;
    float v;
    if (n < 128) {
        v = 0.f;
#pragma unroll
        for (int h = 0; h < 16; h++) v += W[(size_t)(h * 128 + n) * KDIM + c];
        v *= SCALE;
    } else {
        v = W[(size_t)(n + 1920) * KDIM + c];
    }
    bf16 hh, ll; split2(v, hh, ll);
    g_whi[idx] = hh;  g_wlo[idx] = ll;
    if (n >= 640) g_wv16[(size_t)(n - 640) * KDIM + c] = __float2half(v);

    if (idx < NREDC) {
        float bv;
        if (idx < 128) {
            bv = 0.f;
#pragma unroll
            for (int h = 0; h < 16; h++) bv += b[h * 128 + idx];
            bv *= SCALE;
        } else bv = b[idx + 1920];
        g_bred[idx] = bv;
    }
}

// ---------------- projection epilogue scatter ----------------
__device__ __forceinline__ void proj_store(int m, int n, float v0, float v1) {
    if (n < 128) {
        bf16 h0, l0, h1, l1;
        split2(v0, h0, l0);  split2(v1, h1, l1);
        size_t i = (size_t)m * DH + n;
        *(__nv_bfloat162*)&g_qhi[i] = __halves2bfloat162(h0, h1);
        *(__nv_bfloat162*)&g_qlo[i] = __halves2bfloat162(l0, l1);
    } else if (n < 640) {
        bf16 h0, l0, h1, l1;
        split2(v0, h0, l0);  split2(v1, h1, l1);
        int i2 = n - 128;
        int bh = ((m >> 11) << 2) + (i2 >> 7);
        size_t i = (size_t)bh * TT * DH + (size_t)(m & 2047) * DH + (i2 & 127);
        *(__nv_bfloat162*)&g_khi[i] = __halves2bfloat162(h0, h1);
        *(__nv_bfloat162*)&g_klo[i] = __halves2bfloat162(l0, l1);
    } else {
        int i2 = n - 640;
        int bh = ((m >> 11) << 2) + (i2 >> 7);
        size_t i = (size_t)bh * TT * DH + (size_t)(m & 2047) * DH + (i2 & 127);
        *(__half2*)&g_v16[i] = __floats2half2_rn(v0, v1);
    }
}

// ---------------- projection GEMM (R13: 8-warp + fp16 V branch) ----------------
__global__ __launch_bounds__(256, 2)
void gemm_proj(int dummy) {
    extern __shared__ uint16_t sm[];
    constexpr int STAGE = 4 * 4096;

    const int tid  = threadIdx.x;
    const int lane = tid & 31;
    const int warp = tid >> 5;
    const int wm   = warp >> 2;
    const int wn   = warp & 3;
    const int m0   = blockIdx.y * 128;
    const int n0   = blockIdx.x * 128;
    const int KT = KDIM / 32;

    float acc[4][4][4];
#pragma unroll
    for (int mi = 0; mi < 4; mi++)
#pragma unroll
        for (int ni = 0; ni < 4; ni++)
#pragma unroll
            for (int r = 0; r < 4; r++) acc[mi][ni][r] = 0.f;

    if (n0 >= 640) {
        const uint16_t* A = (const uint16_t*)g_x16;
        const uint16_t* B = (const uint16_t*)g_wv16;
        const int nv0 = n0 - 640;

#define LOAD_STAGE_V(kt, buf) do {                                              \
    int k0_ = (kt) * 32;                                                        \
    uint16_t* st_ = sm + (buf) * 8192;                                          \
    _Pragma("unroll")                                                           \
    for (int p = 0; p < 2; p++) {                                               \
        int id = tid + (p << 8);                                                \
        int row = id >> 2, c = id & 3;                                          \
        int so = SWZ(row, c);                                                   \
        cp16(st_ + so,        A + (size_t)(m0 + row) * KDIM + k0_ + (c << 3));  \
        cp16(st_ + 4096 + so, B + (size_t)(nv0 + row) * KDIM + k0_ + (c << 3)); \
    }                                                                           \
} while (0)

        LOAD_STAGE_V(0, 0); CP_COMMIT();
        LOAD_STAGE_V(1, 1); CP_COMMIT();

        int buf = 0;
        for (int kt = 0; kt < KT; kt++) {
            CP_WAIT(1);
            __syncthreads();
            if (kt + 2 < KT) {
                int nb = buf + 2; if (nb >= 3) nb -= 3;
                LOAD_STAGE_V(kt + 2, nb);
                CP_COMMIT();
            }

            const uint16_t* st = sm + buf * 8192;
            unsigned base_a = (unsigned)__cvta_generic_to_shared(st);
            unsigned base_b = base_a + 4096 * 2;

#pragma unroll
            for (int ks = 0; ks < 32; ks += 16) {
                unsigned Af[4][4], Bf[2][4];
                const int chk = (ks >> 3) + (lane >> 4);
#pragma unroll
                for (int mi = 0; mi < 4; mi++) {
                    int r = wm * 64 + mi * 16 + (lane & 15);
                    LDSM4(Af[mi], base_a + SWZ(r, chk) * 2);
                }
#pragma unroll
                for (int bi = 0; bi < 2; bi++) {
                    int r = wn * 32 + bi * 16 + (lane & 15);
                    LDSM4(Bf[bi], base_b + SWZ(r, chk) * 2);
                }
#pragma unroll
                for (int mi = 0; mi < 4; mi++)
#pragma unroll
                    for (int ni = 0; ni < 4; ni++)
                        MMA_F16(acc[mi][ni], Af[mi], Bf[ni >> 1][ni & 1], Bf[ni >> 1][(ni & 1) + 2]);
            }
            buf++; if (buf >= 3) buf = 0;
        }
#undef LOAD_STAGE_V
    } else {
        const uint16_t* Ah = (const uint16_t*)g_xhi;
        const uint16_t* Al = (const uint16_t*)g_xlo;
        const uint16_t* Bh = (const uint16_t*)g_whi;
        const uint16_t* Bl = (const uint16_t*)g_wlo;

#define LOAD_STAGE(kt, buf) do {                                                \
    int k0_ = (kt) * 32;                                                        \
    uint16_t* st_ = sm + (buf) * STAGE;                                         \
    _Pragma("unroll")                                                           \
    for (int p = 0; p < 2; p++) {                                               \
        int id = tid + (p << 8);                                                \
        int row = id >> 2, c = id & 3;                                          \
        int so = SWZ(row, c);                                                   \
        size_t ga = (size_t)(m0 + row) * KDIM + k0_ + (c << 3);                 \
        size_t gb = (size_t)(n0 + row) * KDIM + k0_ + (c << 3);                 \
        cp16(st_ + so,         Ah + ga);                                        \
        cp16(st_ + 4096 + so,  Al + ga);                                        \
        cp16(st_ + 8192 + so,  Bh + gb);                                        \
        cp16(st_ + 12288 + so, Bl + gb);                                        \
    }                                                                           \
} while (0)

        LOAD_STAGE(0, 0); CP_COMMIT();
        LOAD_STAGE(1, 1); CP_COMMIT();

        int buf = 0;
        for (int kt = 0; kt < KT; kt++) {
            CP_WAIT(1);
            __syncthreads();
            if (kt + 2 < KT) {
                int nb = buf + 2; if (nb >= 3) nb -= 3;
                LOAD_STAGE(kt + 2, nb);
                CP_COMMIT();
            }

            const uint16_t* st = sm + buf * STAGE;
            unsigned base_a  = (unsigned)__cvta_generic_to_shared(st);
            unsigned base_al = base_a + 4096 * 2;
            unsigned base_bh = base_a + 8192 * 2;
            unsigned base_bl = base_a + 12288 * 2;

#pragma unroll
            for (int ks = 0; ks < 32; ks += 16) {
                unsigned Af[4][4], Bhf[2][4], Blf[2][4];
                const int chk = (ks >> 3) + (lane >> 4);
#pragma unroll
                for (int mi = 0; mi < 4; mi++) {
                    int r = wm * 64 + mi * 16 + (lane & 15);
                    LDSM4(Af[mi], base_a + SWZ(r, chk) * 2);
                }
#pragma unroll
                for (int bi = 0; bi < 2; bi++) {
                    int r = wn * 32 + bi * 16 + (lane & 15);
                    LDSM4(Bhf[bi], base_bh + SWZ(r, chk) * 2);
                    LDSM4(Blf[bi], base_bl + SWZ(r, chk) * 2);
                }
#pragma unroll
                for (int mi = 0; mi < 4; mi++)
#pragma unroll
                    for (int ni = 0; ni < 4; ni++) {
                        MMA_BF16(acc[mi][ni], Af[mi], Bhf[ni >> 1][ni & 1], Bhf[ni >> 1][(ni & 1) + 2]);
                        MMA_BF16(acc[mi][ni], Af[mi], Blf[ni >> 1][ni & 1], Blf[ni >> 1][(ni & 1) + 2]);
                    }
#pragma unroll
                for (int mi = 0; mi < 4; mi++) {
                    int r = wm * 64 + mi * 16 + (lane & 15);
                    LDSM4(Af[mi], base_al + SWZ(r, chk) * 2);
                }
#pragma unroll
                for (int mi = 0; mi < 4; mi++)
#pragma unroll
                    for (int ni = 0; ni < 4; ni++)
                        MMA_BF16(acc[mi][ni], Af[mi], Bhf[ni >> 1][ni & 1], Bhf[ni >> 1][(ni & 1) + 2]);
            }
            buf++; if (buf >= 3) buf = 0;
        }
#undef LOAD_STAGE
    }

    // ---- shared epilogue ----
#pragma unroll
    for (int mi = 0; mi < 4; mi++)
#pragma unroll
        for (int ni = 0; ni < 4; ni++) {
            int mr = m0 + wm * 64 + mi * 16 + (lane >> 2);
            int nc = n0 + wn * 32 + ni * 8 + ((lane & 3) << 1);
            float* c = acc[mi][ni];
            float b0v = g_bred[nc], b1v = g_bred[nc + 1];
            proj_store(mr,     nc, c[0] + b0v, c[1] + b1v);
            proj_store(mr + 8, nc, c[2] + b0v, c[3] + b1v);
        }
}

// ---------------- fused flash attention: 64-q-row CTAs, 2 CTAs/SM ----------------
// CTA: 64 q rows x one bh. 4 warps; warp w owns q rows w*16..w*16+15.
// KV tiles of 32 keys, TRIPLE-buffered.
// smem (16-bit elems): Qhi[0,8192) Qlo[8192,16384)
//   stage s at 16384+s*12288: Khi[0,4096) Klo[4096,8192) V[8192,12288)
#define FL_STAGE 12288
#define FL_ELEMS (16384 + 3 * FL_STAGE)
#define FL_SMEM  (FL_ELEMS * 2)   // 106496 B = 104 KB -> 2 CTAs/SM

__global__ __launch_bounds__(128)
void flash_attn(float* __restrict__ out) {
    extern __shared__ uint16_t fs[];
    const unsigned sb = (unsigned)__cvta_generic_to_shared(fs);

    const int tid  = threadIdx.x;
    const int lane = tid & 31;
    const int warp = tid >> 5;           // 0..3
    const int bh   = blockIdx.y;
    const int b    = bh >> 2;
    const int kvh  = bh & 3;
    const int q0   = blockIdx.x * 64;

    // ---- load Q (hi+lo): 2048 cp16, 16 per thread ----
    {
        const uint16_t* qsrc0 = (const uint16_t*)g_qhi;
        const uint16_t* qsrc1 = (const uint16_t*)g_qlo;
#pragma unroll
        for (int p = 0; p < 16; p++) {
            int id = tid + (p << 7);
            int part = id >> 10, cid = id & 1023;
            int row = cid >> 4, c8 = cid & 15;
            unsigned dst = (unsigned)(part * 8192 + (c8 >> 2) * 2048 + SWZ(row, c8 & 3));
            const uint16_t* src = (part ? qsrc1 : qsrc0) + (size_t)(b * TT + q0 + row) * DH + c8 * 8;
            cp16s(sb + dst * 2, src);
        }
    }
    CP_COMMIT();

#define LOADKV(kt_, buf_) do {                                                   \
    const uint16_t* ksrc0 = (const uint16_t*)g_khi;                              \
    const uint16_t* ksrc1 = (const uint16_t*)g_klo;                              \
    const uint16_t* vsrc  = (const uint16_t*)g_v16;                              \
    unsigned stg = 16384u + (buf_) * (unsigned)FL_STAGE;                         \
    _Pragma("unroll")                                                            \
    for (int p = 0; p < 12; p++) {                                               \
        int id = tid + (p << 7);                                                 \
        int part = id >> 9, cid = id & 511;                                      \
        int row = cid >> 4, c8 = cid & 15;                                       \
        unsigned dst = stg + part * 4096 + (c8 >> 2) * 1024 + SWZ(row, c8 & 3);  \
        const uint16_t* src = (part == 0 ? ksrc0 : (part == 1 ? ksrc1 : vsrc))   \
            + (size_t)bh * TT * DH + (size_t)((kt_) * 32 + row) * DH + c8 * 8;   \
        cp16s(sb + dst * 2, src);                                                \
    }                                                                            \
} while (0)

    LOADKV(0, 0); CP_COMMIT();
    LOADKV(1, 1); CP_COMMIT();

    float m0s = -1e30f, m1s = -1e30f, l0s = 0.f, l1s = 0.f;
    float O[16][4];
#pragma unroll
    for (int i = 0; i < 16; i++)
#pragma unroll
        for (int j = 0; j < 4; j++) O[i][j] = 0.f;

    const int NT = TT / 32;   // 64 tiles
    int buf = 0;
    for (int kt = 0; kt < NT; kt++) {
        CP_WAIT(1);
        __syncthreads();
        if (kt + 2 < NT) {
            int nb = buf + 2; if (nb >= 3) nb -= 3;
            LOADKV(kt + 2, nb);
            CP_COMMIT();
        }

        const unsigned stgK = sb + (16384u + buf * (unsigned)FL_STAGE) * 2;
        const unsigned stgV = stgK + 8192u * 2;

        // ---- scores: sacc[4][4] = Q . K^T over d=128 (32 keys) ----
        float sacc[4][4];
#pragma unroll
        for (int i = 0; i < 4; i++)
#pragma unroll
            for (int j = 0; j < 4; j++) sacc[i][j] = 0.f;

#pragma unroll
        for (int ks = 0; ks < 8; ks++) {
            const int kc = ks >> 1;
            const int c  = ((ks & 1) << 1) + (lane >> 4);
            unsigned ah[4], al[4], kh[2][4], kl[2][4];
            LDSM4(ah, sb + (0    + kc * 2048 + SWZ(warp * 16 + (lane & 15), c)) * 2);
            LDSM4(al, sb + (8192 + kc * 2048 + SWZ(warp * 16 + (lane & 15), c)) * 2);
#pragma unroll
            for (int nt = 0; nt < 2; nt++) {
                LDSM4(kh[nt], stgK + (kc * 1024 + SWZ(nt * 16 + (lane & 15), c)) * 2);
                LDSM4(kl[nt], stgK + (4096 + kc * 1024 + SWZ(nt * 16 + (lane & 15), c)) * 2);
            }
#pragma unroll
            for (int nt = 0; nt < 2; nt++)
#pragma unroll
                for (int sub = 0; sub < 2; sub++) {
                    int ni = nt * 2 + sub;
                    MMA_BF16(sacc[ni], ah, kh[nt][sub], kh[nt][sub + 2]);
                    MMA_BF16(sacc[ni], al, kh[nt][sub], kh[nt][sub + 2]);
                    MMA_BF16(sacc[ni], ah, kl[nt][sub], kl[nt][sub + 2]);
                }
        }

        // ---- online softmax ----
        float tm0 = -1e30f, tm1 = -1e30f;
#pragma unroll
        for (int ni = 0; ni < 4; ni++) {
            tm0 = fmaxf(tm0, fmaxf(sacc[ni][0], sacc[ni][1]));
            tm1 = fmaxf(tm1, fmaxf(sacc[ni][2], sacc[ni][3]));
        }
        tm0 = fmaxf(tm0, __shfl_xor_sync(~0u, tm0, 1));
        tm0 = fmaxf(tm0, __shfl_xor_sync(~0u, tm0, 2));
        tm1 = fmaxf(tm1, __shfl_xor_sync(~0u, tm1, 1));
        tm1 = fmaxf(tm1, __shfl_xor_sync(~0u, tm1, 2));

        float mn0 = fmaxf(m0s, tm0), mn1 = fmaxf(m1s, tm1);
        float al0 = __expf(m0s - mn0), al1 = __expf(m1s - mn1);
        m0s = mn0; m1s = mn1;

        float rs0 = 0.f, rs1 = 0.f;
#pragma unroll
        for (int ni = 0; ni < 4; ni++) {
            sacc[ni][0] = __expf(sacc[ni][0] - mn0);
            sacc[ni][1] = __expf(sacc[ni][1] - mn0);
            sacc[ni][2] = __expf(sacc[ni][2] - mn1);
            sacc[ni][3] = __expf(sacc[ni][3] - mn1);
            rs0 += sacc[ni][0] + sacc[ni][1];
            rs1 += sacc[ni][2] + sacc[ni][3];
        }
        rs0 += __shfl_xor_sync(~0u, rs0, 1);
        rs0 += __shfl_xor_sync(~0u, rs0, 2);
        rs1 += __shfl_xor_sync(~0u, rs1, 1);
        rs1 += __shfl_xor_sync(~0u, rs1, 2);
        l0s = l0s * al0 + rs0;
        l1s = l1s * al1 + rs1;

#pragma unroll
        for (int dj = 0; dj < 16; dj++) {
            O[dj][0] *= al0; O[dj][1] *= al0;
            O[dj][2] *= al1; O[dj][3] *= al1;
        }

        // ---- PV: O += P(fp16 regs) x V (trans-ldmatrix from [t][d]) ----
#pragma unroll
        for (int kt2 = 0; kt2 < 2; kt2++) {
            unsigned pa[4];
            pa[0] = h2u(__floats2half2_rn(sacc[kt2 * 2][0],     sacc[kt2 * 2][1]));
            pa[1] = h2u(__floats2half2_rn(sacc[kt2 * 2][2],     sacc[kt2 * 2][3]));
            pa[2] = h2u(__floats2half2_rn(sacc[kt2 * 2 + 1][0], sacc[kt2 * 2 + 1][1]));
            pa[3] = h2u(__floats2half2_rn(sacc[kt2 * 2 + 1][2], sacc[kt2 * 2 + 1][3]));
#pragma unroll
            for (int dt = 0; dt < 8; dt++) {
                unsigned v[4];
                const int chunk = dt >> 1;
                const int c = ((dt & 1) << 1) + (lane >> 4);
                LDSM4T(v, stgV + (chunk * 1024 + SWZ(kt2 * 16 + (lane & 15), c)) * 2);
                MMA_F16(O[dt * 2],     pa, v[0], v[1]);
                MMA_F16(O[dt * 2 + 1], pa, v[2], v[3]);
            }
        }

        buf++; if (buf >= 3) buf = 0;
    }
#undef LOADKV

    // ---- epilogue ----
    float inv0 = 1.f / l0s, inv1 = 1.f / l1s;
    int r = warp * 16 + (lane >> 2);
    float* o0 = out + (size_t)(b * TT + q0 + r) * 512 + kvh * 128;
    float* o1 = o0 + 8 * 512;
#pragma unroll
    for (int dj = 0; dj < 16; dj++) {
        int d = dj * 8 + ((lane & 3) << 1);
        *(float2*)(o0 + d) = make_float2(O[dj][0] * inv0, O[dj][1] * inv0);
        *(float2*)(o1 + d) = make_float2(O[dj][2] * inv1, O[dj][3] * inv1);
    }
}

// ---------------- launch ----------------
extern "C" void kernel_launch(void* const* d_in, const int* in_sizes, int n_in,
                              void* d_out, int out_size) {
    (void)in_sizes; (void)n_in; (void)out_size;
    const float* x = (const float*)d_in[0];
    const float* W = (const float*)d_in[1];
    const float* b = (const float*)d_in[2];
    float* out = (float*)d_out;

    const int SMEM_AB = 3 * 4 * 4096 * 2;   // 96KB
    cudaFuncSetAttribute(gemm_proj, cudaFuncAttributeMaxDynamicSharedMemorySize, SMEM_AB);
    cudaFuncSetAttribute(flash_attn, cudaFuncAttributeMaxDynamicSharedMemorySize, FL_SMEM);

    prep_x<<<16384, 256>>>(x);
    prep_w<<<9216, 256>>>(W, b);
    gemm_proj<<<dim3(9, 64), 256, SMEM_AB>>>(0);
    flash_attn<<<dim3(TT / 64, 16), 128, FL_SMEM>>>(out);
}

// round 15
// speedup vs baseline: 1.0675x; 1.0675x over previous
#include <cuda_runtime.h>
#include <cuda_bf16.h>
#include <cuda_fp16.h>
#include <cstdint>
#include <math.h>

typedef __nv_bfloat16 bf16;

#define TT    2048
#define KDIM  2048
#define DH    128
#define NREDC 1152
#define MROWS 8192
#define NBH   16
#define SCALE 0.08838834764831845f   // 1/sqrt(128)

// ---------------- device scratch ----------------
__device__ bf16   g_xhi[(size_t)MROWS*KDIM];
__device__ bf16   g_xlo[(size_t)MROWS*KDIM];
__device__ __half g_x16[(size_t)MROWS*KDIM];     // x single fp16 (V-GEMM)
__device__ bf16   g_whi[(size_t)NREDC*KDIM];
__device__ bf16   g_wlo[(size_t)NREDC*KDIM];
__device__ __half g_wv16[(size_t)512*KDIM];      // V weights fp16 (rows n-640)
__device__ float  g_bred[NREDC];
__device__ bf16   g_qhi[(size_t)MROWS*DH];
__device__ bf16   g_qlo[(size_t)MROWS*DH];
__device__ bf16   g_khi[(size_t)NBH*TT*DH];
__device__ bf16   g_klo[(size_t)NBH*TT*DH];
__device__ __half g_v16[(size_t)NBH*TT*DH];      // V [bh][t][d], single fp16

// ---------------- helpers ----------------
__device__ __forceinline__ void split2(float v, bf16& h, bf16& l) {
    h = __float2bfloat16(v);
    l = __float2bfloat16(v - __bfloat162float(h));
}
__device__ __forceinline__ unsigned h2u(__half2 h) {
    return *reinterpret_cast<unsigned*>(&h);
}
__device__ __forceinline__ void cp16(void* sp, const void* gp) {
    unsigned s = (unsigned)__cvta_generic_to_shared(sp);
    asm volatile("cp.async.cg.shared.global [%0], [%1], 16;\n" :: "r"(s), "l"(gp));
}
__device__ __forceinline__ void cp16s(unsigned s, const void* gp) {
    asm volatile("cp.async.cg.shared.global [%0], [%1], 16;\n" :: "r"(s), "l"(gp));
}
#define CP_COMMIT() asm volatile("cp.async.commit_group;\n")
#define CP_WAIT(n)  asm volatile("cp.async.wait_group %0;\n" :: "n"(n))

// swizzled element offset inside an Nx32 16-bit tile (64B rows, 16B chunks)
#define SWZ(r, c) (((r) << 5) + ((((c) ^ (((r) >> 1) & 3))) << 3))

#define LDSM4(R, addr) \
    asm volatile("ldmatrix.sync.aligned.m8n8.x4.shared.b16 {%0,%1,%2,%3}, [%4];" \
        : "=r"((R)[0]), "=r"((R)[1]), "=r"((R)[2]), "=r"((R)[3]) : "r"(addr))

#define LDSM4T(R, addr) \
    asm volatile("ldmatrix.sync.aligned.m8n8.x4.trans.shared.b16 {%0,%1,%2,%3}, [%4];" \
        : "=r"((R)[0]), "=r"((R)[1]), "=r"((R)[2]), "=r"((R)[3]) : "r"(addr))

#define MMA_BF16(C, A, b0, b1) \
    asm volatile("mma.sync.aligned.m16n8k16.row.col.f32.bf16.bf16.f32 " \
        "{%0,%1,%2,%3},{%4,%5,%6,%7},{%8,%9},{%0,%1,%2,%3};" \
        : "+f"((C)[0]), "+f"((C)[1]), "+f"((C)[2]), "+f"((C)[3]) \
        : "r"((A)[0]), "r"((A)[1]), "r"((A)[2]), "r"((A)[3]), "r"(b0), "r"(b1))

#define MMA_F16(C, A, b0, b1) \
    asm volatile("mma.sync.aligned.m16n8k16.row.col.f32.f16.f16.f32 " \
        "{%0,%1,%2,%3},{%4,%5,%6,%7},{%8,%9},{%0,%1,%2,%3};" \
        : "+f"((C)[0]), "+f"((C)[1]), "+f"((C)[2]), "+f"((C)[3]) \
        : "r"((A)[0]), "r"((A)[1]), "r"((A)[2]), "r"((A)[3]), "r"(b0), "r"(b1))

// ---------------- merged prep: blocks [0,16384) = x, rest = w ----------------
__global__ void prep_xw(const float* __restrict__ x,
                        const float* __restrict__ W,
                        const float* __restrict__ b) {
    if (blockIdx.x < 16384) {
        size_t i = ((size_t)blockIdx.x * 256 + threadIdx.x) * 4;
        float4 a = *(const float4*)(x + i);
        float arr[4] = {a.x, a.y, a.z, a.w};
#pragma unroll
        for (int j = 0; j < 4; j++) {
            bf16 h, l; split2(arr[j], h, l);
            g_xhi[i + j] = h;  g_xlo[i + j] = l;
            g_x16[i + j] = __float2half(arr[j]);
        }
    } else {
        int idx = (blockIdx.x - 16384) * 256 + threadIdx.x;
        int n = idx >> 11, c = idx & 2047;
        float v;
        if (n < 128) {
            v = 0.f;
#pragma unroll
            for (int h = 0; h < 16; h++) v += W[(size_t)(h * 128 + n) * KDIM + c];
            v *= SCALE;
        } else {
            v = W[(size_t)(n + 1920) * KDIM + c];
        }
        bf16 hh, ll; split2(v, hh, ll);
        g_whi[idx] = hh;  g_wlo[idx] = ll;
        if (n >= 640) g_wv16[(size_t)(n - 640) * KDIM + c] = __float2half(v);

        if (idx < NREDC) {
            float bv;
            if (idx < 128) {
                bv = 0.f;
#pragma unroll
                for (int h = 0; h < 16; h++) bv += b[h * 128 + idx];
                bv *= SCALE;
            } else bv = b[idx + 1920];
            g_bred[idx] = bv;
        }
    }
}

// ---------------- projection epilogue scatter ----------------
__device__ __forceinline__ void proj_store(int m, int n, float v0, float v1) {
    if (n < 128) {
        bf16 h0, l0, h1, l1;
        split2(v0, h0, l0);  split2(v1, h1, l1);
        size_t i = (size_t)m * DH + n;
        *(__nv_bfloat162*)&g_qhi[i] = __halves2bfloat162(h0, h1);
        *(__nv_bfloat162*)&g_qlo[i] = __halves2bfloat162(l0, l1);
    } else if (n < 640) {
        bf16 h0, l0, h1, l1;
        split2(v0, h0, l0);  split2(v1, h1, l1);
        int i2 = n - 128;
        int bh = ((m >> 11) << 2) + (i2 >> 7);
        size_t i = (size_t)bh * TT * DH + (size_t)(m & 2047) * DH + (i2 & 127);
        *(__nv_bfloat162*)&g_khi[i] = __halves2bfloat162(h0, h1);
        *(__nv_bfloat162*)&g_klo[i] = __halves2bfloat162(l0, l1);
    } else {
        int i2 = n - 640;
        int bh = ((m >> 11) << 2) + (i2 >> 7);
        size_t i = (size_t)bh * TT * DH + (size_t)(m & 2047) * DH + (i2 & 127);
        *(__half2*)&g_v16[i] = __floats2half2_rn(v0, v1);
    }
}

// ---------------- projection GEMM (R13: 8-warp + fp16 V branch) ----------------
__global__ __launch_bounds__(256, 2)
void gemm_proj(int dummy) {
    extern __shared__ uint16_t sm[];
    constexpr int STAGE = 4 * 4096;

    const int tid  = threadIdx.x;
    const int lane = tid & 31;
    const int warp = tid >> 5;
    const int wm   = warp >> 2;
    const int wn   = warp & 3;
    const int m0   = blockIdx.y * 128;
    const int n0   = blockIdx.x * 128;
    const int KT = KDIM / 32;

    float acc[4][4][4];
#pragma unroll
    for (int mi = 0; mi < 4; mi++)
#pragma unroll
        for (int ni = 0; ni < 4; ni++)
#pragma unroll
            for (int r = 0; r < 4; r++) acc[mi][ni][r] = 0.f;

    if (n0 >= 640) {
        const uint16_t* A = (const uint16_t*)g_x16;
        const uint16_t* B = (const uint16_t*)g_wv16;
        const int nv0 = n0 - 640;

#define LOAD_STAGE_V(kt, buf) do {                                              \
    int k0_ = (kt) * 32;                                                        \
    uint16_t* st_ = sm + (buf) * 8192;                                          \
    _Pragma("unroll")                                                           \
    for (int p = 0; p < 2; p++) {                                               \
        int id = tid + (p << 8);                                                \
        int row = id >> 2, c = id & 3;                                          \
        int so = SWZ(row, c);                                                   \
        cp16(st_ + so,        A + (size_t)(m0 + row) * KDIM + k0_ + (c << 3));  \
        cp16(st_ + 4096 + so, B + (size_t)(nv0 + row) * KDIM + k0_ + (c << 3)); \
    }                                                                           \
} while (0)

        LOAD_STAGE_V(0, 0); CP_COMMIT();
        LOAD_STAGE_V(1, 1); CP_COMMIT();

        int buf = 0;
        for (int kt = 0; kt < KT; kt++) {
            CP_WAIT(1);
            __syncthreads();
            if (kt + 2 < KT) {
                int nb = buf + 2; if (nb >= 3) nb -= 3;
                LOAD_STAGE_V(kt + 2, nb);
                CP_COMMIT();
            }

            const uint16_t* st = sm + buf * 8192;
            unsigned base_a = (unsigned)__cvta_generic_to_shared(st);
            unsigned base_b = base_a + 4096 * 2;

#pragma unroll
            for (int ks = 0; ks < 32; ks += 16) {
                unsigned Af[4][4], Bf[2][4];
                const int chk = (ks >> 3) + (lane >> 4);
#pragma unroll
                for (int mi = 0; mi < 4; mi++) {
                    int r = wm * 64 + mi * 16 + (lane & 15);
                    LDSM4(Af[mi], base_a + SWZ(r, chk) * 2);
                }
#pragma unroll
                for (int bi = 0; bi < 2; bi++) {
                    int r = wn * 32 + bi * 16 + (lane & 15);
                    LDSM4(Bf[bi], base_b + SWZ(r, chk) * 2);
                }
#pragma unroll
                for (int mi = 0; mi < 4; mi++)
#pragma unroll
                    for (int ni = 0; ni < 4; ni++)
                        MMA_F16(acc[mi][ni], Af[mi], Bf[ni >> 1][ni & 1], Bf[ni >> 1][(ni & 1) + 2]);
            }
            buf++; if (buf >= 3) buf = 0;
        }
#undef LOAD_STAGE_V
    } else {
        const uint16_t* Ah = (const uint16_t*)g_xhi;
        const uint16_t* Al = (const uint16_t*)g_xlo;
        const uint16_t* Bh = (const uint16_t*)g_whi;
        const uint16_t* Bl = (const uint16_t*)g_wlo;

#define LOAD_STAGE(kt, buf) do {                                                \
    int k0_ = (kt) * 32;                                                        \
    uint16_t* st_ = sm + (buf) * STAGE;                                         \
    _Pragma("unroll")                                                           \
    for (int p = 0; p < 2; p++) {                                               \
        int id = tid + (p << 8);                                                \
        int row = id >> 2, c = id & 3;                                          \
        int so = SWZ(row, c);                                                   \
        size_t ga = (size_t)(m0 + row) * KDIM + k0_ + (c << 3);                 \
        size_t gb = (size_t)(n0 + row) * KDIM + k0_ + (c << 3);                 \
        cp16(st_ + so,         Ah + ga);                                        \
        cp16(st_ + 4096 + so,  Al + ga);                                        \
        cp16(st_ + 8192 + so,  Bh + gb);                                        \
        cp16(st_ + 12288 + so, Bl + gb);                                        \
    }                                                                           \
} while (0)

        LOAD_STAGE(0, 0); CP_COMMIT();
        LOAD_STAGE(1, 1); CP_COMMIT();

        int buf = 0;
        for (int kt = 0; kt < KT; kt++) {
            CP_WAIT(1);
            __syncthreads();
            if (kt + 2 < KT) {
                int nb = buf + 2; if (nb >= 3) nb -= 3;
                LOAD_STAGE(kt + 2, nb);
                CP_COMMIT();
            }

            const uint16_t* st = sm + buf * STAGE;
            unsigned base_a  = (unsigned)__cvta_generic_to_shared(st);
            unsigned base_al = base_a + 4096 * 2;
            unsigned base_bh = base_a + 8192 * 2;
            unsigned base_bl = base_a + 12288 * 2;

#pragma unroll
            for (int ks = 0; ks < 32; ks += 16) {
                unsigned Af[4][4], Bhf[2][4], Blf[2][4];
                const int chk = (ks >> 3) + (lane >> 4);
#pragma unroll
                for (int mi = 0; mi < 4; mi++) {
                    int r = wm * 64 + mi * 16 + (lane & 15);
                    LDSM4(Af[mi], base_a + SWZ(r, chk) * 2);
                }
#pragma unroll
                for (int bi = 0; bi < 2; bi++) {
                    int r = wn * 32 + bi * 16 + (lane & 15);
                    LDSM4(Bhf[bi], base_bh + SWZ(r, chk) * 2);
                    LDSM4(Blf[bi], base_bl + SWZ(r, chk) * 2);
                }
#pragma unroll
                for (int mi = 0; mi < 4; mi++)
#pragma unroll
                    for (int ni = 0; ni < 4; ni++) {
                        MMA_BF16(acc[mi][ni], Af[mi], Bhf[ni >> 1][ni & 1], Bhf[ni >> 1][(ni & 1) + 2]);
                        MMA_BF16(acc[mi][ni], Af[mi], Blf[ni >> 1][ni & 1], Blf[ni >> 1][(ni & 1) + 2]);
                    }
#pragma unroll
                for (int mi = 0; mi < 4; mi++) {
                    int r = wm * 64 + mi * 16 + (lane & 15);
                    LDSM4(Af[mi], base_al + SWZ(r, chk) * 2);
                }
#pragma unroll
                for (int mi = 0; mi < 4; mi++)
#pragma unroll
                    for (int ni = 0; ni < 4; ni++)
                        MMA_BF16(acc[mi][ni], Af[mi], Bhf[ni >> 1][ni & 1], Bhf[ni >> 1][(ni & 1) + 2]);
            }
            buf++; if (buf >= 3) buf = 0;
        }
#undef LOAD_STAGE
    }

    // ---- shared epilogue ----
#pragma unroll
    for (int mi = 0; mi < 4; mi++)
#pragma unroll
        for (int ni = 0; ni < 4; ni++) {
            int mr = m0 + wm * 64 + mi * 16 + (lane >> 2);
            int nc = n0 + wn * 32 + ni * 8 + ((lane & 3) << 1);
            float* c = acc[mi][ni];
            float b0v = g_bred[nc], b1v = g_bred[nc + 1];
            proj_store(mr,     nc, c[0] + b0v, c[1] + b1v);
            proj_store(mr + 8, nc, c[2] + b0v, c[3] + b1v);
        }
}

// ---------------- fused flash attention (exact R8/R13 structure) ----------------
#define FL_STAGE 24576
#define FL_ELEMS (32768 + 3 * FL_STAGE)
#define FL_SMEM  (FL_ELEMS * 2)

__global__ __launch_bounds__(256)
void flash_attn(float* __restrict__ out) {
    extern __shared__ uint16_t fs[];
    const unsigned sb = (unsigned)__cvta_generic_to_shared(fs);

    const int tid  = threadIdx.x;
    const int lane = tid & 31;
    const int warp = tid >> 5;
    const int bh   = blockIdx.y;
    const int b    = bh >> 2;
    const int kvh  = bh & 3;
    const int q0   = blockIdx.x * 128;

    // ---- load Q (hi+lo) to smem ----
    {
        const uint16_t* qsrc0 = (const uint16_t*)g_qhi;
        const uint16_t* qsrc1 = (const uint16_t*)g_qlo;
#pragma unroll
        for (int p = 0; p < 16; p++) {
            int id = tid + (p << 8);
            int part = id >> 11, cid = id & 2047;
            int row = cid >> 4, c8 = cid & 15;
            unsigned dst = (unsigned)(part * 16384 + (c8 >> 2) * 4096 + SWZ(row, c8 & 3));
            const uint16_t* src = (part ? qsrc1 : qsrc0) + (size_t)(b * TT + q0 + row) * DH + c8 * 8;
            cp16s(sb + dst * 2, src);
        }
    }
    CP_COMMIT();

#define LOADKV(kt_, buf_) do {                                                   \
    const uint16_t* ksrc0 = (const uint16_t*)g_khi;                              \
    const uint16_t* ksrc1 = (const uint16_t*)g_klo;                              \
    const uint16_t* vsrc  = (const uint16_t*)g_v16;                              \
    unsigned stg = 32768u + (buf_) * (unsigned)FL_STAGE;                         \
    _Pragma("unroll")                                                            \
    for (int p = 0; p < 12; p++) {                                               \
        int id = tid + (p << 8);                                                 \
        int part = id >> 10, cid = id & 1023;                                    \
        int row = cid >> 4, c8 = cid & 15;                                       \
        unsigned dst = stg + part * 8192 + (c8 >> 2) * 2048 + SWZ(row, c8 & 3);  \
        const uint16_t* src = (part == 0 ? ksrc0 : (part == 1 ? ksrc1 : vsrc))   \
            + (size_t)bh * TT * DH + (size_t)((kt_) * 64 + row) * DH + c8 * 8;   \
        cp16s(sb + dst * 2, src);                                                \
    }                                                                            \
} while (0)

    LOADKV(0, 0); CP_COMMIT();
    LOADKV(1, 1); CP_COMMIT();

    float m0s = -1e30f, m1s = -1e30f, l0s = 0.f, l1s = 0.f;
    float O[16][4];
#pragma unroll
    for (int i = 0; i < 16; i++)
#pragma unroll
        for (int j = 0; j < 4; j++) O[i][j] = 0.f;

    const int NT = TT / 64;   // 32 tiles
    int buf = 0;
    for (int kt = 0; kt < NT; kt++) {
        CP_WAIT(1);
        __syncthreads();
        if (kt + 2 < NT) {
            int nb = buf + 2; if (nb >= 3) nb -= 3;
            LOADKV(kt + 2, nb);
            CP_COMMIT();
        }

        const unsigned stgK = sb + (32768u + buf * (unsigned)FL_STAGE) * 2;
        const unsigned stgV = stgK + 16384u * 2;

        // ---- scores: sacc[8][4] = Q . K^T over d=128 ----
        float sacc[8][4];
#pragma unroll
        for (int i = 0; i < 8; i++)
#pragma unroll
            for (int j = 0; j < 4; j++) sacc[i][j] = 0.f;

#pragma unroll
        for (int ks = 0; ks < 8; ks++) {
            const int kc = ks >> 1;
            const int c  = ((ks & 1) << 1) + (lane >> 4);
            unsigned ah[4], al[4], kh[4][4], kl[4][4];
            LDSM4(ah, sb + (0     + kc * 4096 + SWZ(warp * 16 + (lane & 15), c)) * 2);
            LDSM4(al, sb + (16384 + kc * 4096 + SWZ(warp * 16 + (lane & 15), c)) * 2);
#pragma unroll
            for (int nt = 0; nt < 4; nt++) {
                LDSM4(kh[nt], stgK + (kc * 2048 + SWZ(nt * 16 + (lane & 15), c)) * 2);
                LDSM4(kl[nt], stgK + (8192 + kc * 2048 + SWZ(nt * 16 + (lane & 15), c)) * 2);
            }
#pragma unroll
            for (int nt = 0; nt < 4; nt++)
#pragma unroll
                for (int sub = 0; sub < 2; sub++) {
                    int ni = nt * 2 + sub;
                    MMA_BF16(sacc[ni], ah, kh[nt][sub], kh[nt][sub + 2]);
                    MMA_BF16(sacc[ni], al, kh[nt][sub], kh[nt][sub + 2]);
                    MMA_BF16(sacc[ni], ah, kl[nt][sub], kl[nt][sub + 2]);
                }
        }

        // ---- online softmax ----
        float tm0 = -1e30f, tm1 = -1e30f;
#pragma unroll
        for (int ni = 0; ni < 8; ni++) {
            tm0 = fmaxf(tm0, fmaxf(sacc[ni][0], sacc[ni][1]));
            tm1 = fmaxf(tm1, fmaxf(sacc[ni][2], sacc[ni][3]));
        }
        tm0 = fmaxf(tm0, __shfl_xor_sync(~0u, tm0, 1));
        tm0 = fmaxf(tm0, __shfl_xor_sync(~0u, tm0, 2));
        tm1 = fmaxf(tm1, __shfl_xor_sync(~0u, tm1, 1));
        tm1 = fmaxf(tm1, __shfl_xor_sync(~0u, tm1, 2));

        float mn0 = fmaxf(m0s, tm0), mn1 = fmaxf(m1s, tm1);
        float al0 = __expf(m0s - mn0), al1 = __expf(m1s - mn1);
        m0s = mn0; m1s = mn1;

        float rs0 = 0.f, rs1 = 0.f;
#pragma unroll
        for (int ni = 0; ni < 8; ni++) {
            sacc[ni][0] = __expf(sacc[ni][0] - mn0);
            sacc[ni][1] = __expf(sacc[ni][1] - mn0);
            sacc[ni][2] = __expf(sacc[ni][2] - mn1);
            sacc[ni][3] = __expf(sacc[ni][3] - mn1);
            rs0 += sacc[ni][0] + sacc[ni][1];
            rs1 += sacc[ni][2] + sacc[ni][3];
        }
        rs0 += __shfl_xor_sync(~0u, rs0, 1);
        rs0 += __shfl_xor_sync(~0u, rs0, 2);
        rs1 += __shfl_xor_sync(~0u, rs1, 1);
        rs1 += __shfl_xor_sync(~0u, rs1, 2);
        l0s = l0s * al0 + rs0;
        l1s = l1s * al1 + rs1;

#pragma unroll
        for (int dj = 0; dj < 16; dj++) {
            O[dj][0] *= al0; O[dj][1] *= al0;
            O[dj][2] *= al1; O[dj][3] *= al1;
        }

        // ---- PV: O += P(fp16 regs) x V (trans-ldmatrix from [t][d]) ----
#pragma unroll
        for (int kt2 = 0; kt2 < 4; kt2++) {
            unsigned pa[4];
            pa[0] = h2u(__floats2half2_rn(sacc[kt2 * 2][0],     sacc[kt2 * 2][1]));
            pa[1] = h2u(__floats2half2_rn(sacc[kt2 * 2][2],     sacc[kt2 * 2][3]));
            pa[2] = h2u(__floats2half2_rn(sacc[kt2 * 2 + 1][0], sacc[kt2 * 2 + 1][1]));
            pa[3] = h2u(__floats2half2_rn(sacc[kt2 * 2 + 1][2], sacc[kt2 * 2 + 1][3]));
#pragma unroll
            for (int dt = 0; dt < 8; dt++) {
                unsigned v[4];
                const int chunk = dt >> 1;
                const int c = ((dt & 1) << 1) + (lane >> 4);
                LDSM4T(v, stgV + (chunk * 2048 + SWZ(kt2 * 16 + (lane & 15), c)) * 2);
                MMA_F16(O[dt * 2],     pa, v[0], v[1]);
                MMA_F16(O[dt * 2 + 1], pa, v[2], v[3]);
            }
        }

        buf++; if (buf >= 3) buf = 0;
    }
#undef LOADKV

    // ---- epilogue ----
    float inv0 = 1.f / l0s, inv1 = 1.f / l1s;
    int r = warp * 16 + (lane >> 2);
    float* o0 = out + (size_t)(b * TT + q0 + r) * 512 + kvh * 128;
    float* o1 = o0 + 8 * 512;
#pragma unroll
    for (int dj = 0; dj < 16; dj++) {
        int d = dj * 8 + ((lane & 3) << 1);
        *(float2*)(o0 + d) = make_float2(O[dj][0] * inv0, O[dj][1] * inv0);
        *(float2*)(o1 + d) = make_float2(O[dj][2] * inv1, O[dj][3] * inv1);
    }
}

// ---------------- launch ----------------
extern "C" void kernel_launch(void* const* d_in, const int* in_sizes, int n_in,
                              void* d_out, int out_size) {
    (void)in_sizes; (void)n_in; (void)out_size;
    const float* x = (const float*)d_in[0];
    const float* W = (const float*)d_in[1];
    const float* b = (const float*)d_in[2];
    float* out = (float*)d_out;

    const int SMEM_AB = 3 * 4 * 4096 * 2;   // 96KB
    cudaFuncSetAttribute(gemm_proj, cudaFuncAttributeMaxDynamicSharedMemorySize, SMEM_AB);
    cudaFuncSetAttribute(flash_attn, cudaFuncAttributeMaxDynamicSharedMemorySize, FL_SMEM);

    prep_xw<<<16384 + 9216, 256>>>(x, W, b);
    gemm_proj<<<dim3(9, 64), 256, SMEM_AB>>>(0);
    flash_attn<<<dim3(16, 16), 256, FL_SMEM>>>(out);
}

// round 16
// speedup vs baseline: 1.1440x; 1.0716x over previous
#include <cuda_runtime.h>
#include <cuda_bf16.h>
#include <cuda_fp16.h>
#include <cstdint>
#include <math.h>

typedef __nv_bfloat16 bf16;

#define TT    2048
#define KDIM  2048
#define DH    128
#define NREDC 1152
#define MROWS 8192
#define NBH   16
#define SCALE 0.08838834764831845f   // 1/sqrt(128)

// ---------------- device scratch ----------------
__device__ bf16   g_xhi[(size_t)MROWS*KDIM];
__device__ bf16   g_xlo[(size_t)MROWS*KDIM];
__device__ __half g_x16[(size_t)MROWS*KDIM];     // x single fp16 (V-GEMM)
__device__ bf16   g_whi[(size_t)NREDC*KDIM];
__device__ bf16   g_wlo[(size_t)NREDC*KDIM];
__device__ __half g_wv16[(size_t)512*KDIM];      // V weights fp16 (rows n-640)
__device__ float  g_bred[NREDC];
__device__ bf16   g_qhi[(size_t)MROWS*DH];
__device__ bf16   g_qlo[(size_t)MROWS*DH];
__device__ bf16   g_khi[(size_t)NBH*TT*DH];
__device__ bf16   g_klo[(size_t)NBH*TT*DH];
__device__ __half g_v16[(size_t)NBH*TT*DH];      // V [bh][t][d], single fp16

// ---------------- helpers ----------------
__device__ __forceinline__ void split2(float v, bf16& h, bf16& l) {
    h = __float2bfloat16(v);
    l = __float2bfloat16(v - __bfloat162float(h));
}
__device__ __forceinline__ unsigned h2u(__half2 h) {
    return *reinterpret_cast<unsigned*>(&h);
}
__device__ __forceinline__ unsigned b2u(__nv_bfloat162 h) {
    return *reinterpret_cast<unsigned*>(&h);
}
__device__ __forceinline__ void cp16(void* sp, const void* gp) {
    unsigned s = (unsigned)__cvta_generic_to_shared(sp);
    asm volatile("cp.async.cg.shared.global [%0], [%1], 16;\n" :: "r"(s), "l"(gp));
}
__device__ __forceinline__ void cp16s(unsigned s, const void* gp) {
    asm volatile("cp.async.cg.shared.global [%0], [%1], 16;\n" :: "r"(s), "l"(gp));
}
#define CP_COMMIT() asm volatile("cp.async.commit_group;\n")
#define CP_WAIT(n)  asm volatile("cp.async.wait_group %0;\n" :: "n"(n))

// swizzled element offset inside an Nx32 16-bit tile (64B rows, 16B chunks)
#define SWZ(r, c) (((r) << 5) + ((((c) ^ (((r) >> 1) & 3))) << 3))

#define LDSM4(R, addr) \
    asm volatile("ldmatrix.sync.aligned.m8n8.x4.shared.b16 {%0,%1,%2,%3}, [%4];" \
        : "=r"((R)[0]), "=r"((R)[1]), "=r"((R)[2]), "=r"((R)[3]) : "r"(addr))

#define LDSM4T(R, addr) \
    asm volatile("ldmatrix.sync.aligned.m8n8.x4.trans.shared.b16 {%0,%1,%2,%3}, [%4];" \
        : "=r"((R)[0]), "=r"((R)[1]), "=r"((R)[2]), "=r"((R)[3]) : "r"(addr))

#define MMA_BF16(C, A, b0, b1) \
    asm volatile("mma.sync.aligned.m16n8k16.row.col.f32.bf16.bf16.f32 " \
        "{%0,%1,%2,%3},{%4,%5,%6,%7},{%8,%9},{%0,%1,%2,%3};" \
        : "+f"((C)[0]), "+f"((C)[1]), "+f"((C)[2]), "+f"((C)[3]) \
        : "r"((A)[0]), "r"((A)[1]), "r"((A)[2]), "r"((A)[3]), "r"(b0), "r"(b1))

#define MMA_F16(C, A, b0, b1) \
    asm volatile("mma.sync.aligned.m16n8k16.row.col.f32.f16.f16.f32 " \
        "{%0,%1,%2,%3},{%4,%5,%6,%7},{%8,%9},{%0,%1,%2,%3};" \
        : "+f"((C)[0]), "+f"((C)[1]), "+f"((C)[2]), "+f"((C)[3]) \
        : "r"((A)[0]), "r"((A)[1]), "r"((A)[2]), "r"((A)[3]), "r"(b0), "r"(b1))

// ---------------- merged prep: blocks [0,8192) = x (8 elems/thread), rest = w ----------------
__global__ void prep_xw(const float* __restrict__ x,
                        const float* __restrict__ W,
                        const float* __restrict__ b) {
    if (blockIdx.x < 8192) {
        size_t i = ((size_t)blockIdx.x * 256 + threadIdx.x) * 8;
        float4 a0 = *(const float4*)(x + i);
        float4 a1 = *(const float4*)(x + i + 4);
        float arr[8] = {a0.x, a0.y, a0.z, a0.w, a1.x, a1.y, a1.z, a1.w};
        bf16 hh[8], ll[8];
        unsigned hx[4];
#pragma unroll
        for (int j = 0; j < 8; j++) split2(arr[j], hh[j], ll[j]);
#pragma unroll
        for (int j = 0; j < 4; j++)
            hx[j] = h2u(__floats2half2_rn(arr[j * 2], arr[j * 2 + 1]));
        uint4 vh, vl;
        vh.x = b2u(__halves2bfloat162(hh[0], hh[1]));
        vh.y = b2u(__halves2bfloat162(hh[2], hh[3]));
        vh.z = b2u(__halves2bfloat162(hh[4], hh[5]));
        vh.w = b2u(__halves2bfloat162(hh[6], hh[7]));
        vl.x = b2u(__halves2bfloat162(ll[0], ll[1]));
        vl.y = b2u(__halves2bfloat162(ll[2], ll[3]));
        vl.z = b2u(__halves2bfloat162(ll[4], ll[5]));
        vl.w = b2u(__halves2bfloat162(ll[6], ll[7]));
        *(uint4*)&g_xhi[i] = vh;
        *(uint4*)&g_xlo[i] = vl;
        *(uint4*)&g_x16[i] = make_uint4(hx[0], hx[1], hx[2], hx[3]);
    } else {
        int idx = (blockIdx.x - 8192) * 256 + threadIdx.x;
        int n = idx >> 11, c = idx & 2047;
        float v;
        if (n < 128) {
            v = 0.f;
#pragma unroll
            for (int h = 0; h < 16; h++) v += W[(size_t)(h * 128 + n) * KDIM + c];
            v *= SCALE;
        } else {
            v = W[(size_t)(n + 1920) * KDIM + c];
        }
        bf16 hh, ll; split2(v, hh, ll);
        g_whi[idx] = hh;  g_wlo[idx] = ll;
        if (n >= 640) g_wv16[(size_t)(n - 640) * KDIM + c] = __float2half(v);

        if (idx < NREDC) {
            float bv;
            if (idx < 128) {
                bv = 0.f;
#pragma unroll
                for (int h = 0; h < 16; h++) bv += b[h * 128 + idx];
                bv *= SCALE;
            } else bv = b[idx + 1920];
            g_bred[idx] = bv;
        }
    }
}

// ---------------- projection epilogue scatter ----------------
__device__ __forceinline__ void proj_store(int m, int n, float v0, float v1) {
    if (n < 128) {
        bf16 h0, l0, h1, l1;
        split2(v0, h0, l0);  split2(v1, h1, l1);
        size_t i = (size_t)m * DH + n;
        *(__nv_bfloat162*)&g_qhi[i] = __halves2bfloat162(h0, h1);
        *(__nv_bfloat162*)&g_qlo[i] = __halves2bfloat162(l0, l1);
    } else if (n < 640) {
        bf16 h0, l0, h1, l1;
        split2(v0, h0, l0);  split2(v1, h1, l1);
        int i2 = n - 128;
        int bh = ((m >> 11) << 2) + (i2 >> 7);
        size_t i = (size_t)bh * TT * DH + (size_t)(m & 2047) * DH + (i2 & 127);
        *(__nv_bfloat162*)&g_khi[i] = __halves2bfloat162(h0, h1);
        *(__nv_bfloat162*)&g_klo[i] = __halves2bfloat162(l0, l1);
    } else {
        int i2 = n - 640;
        int bh = ((m >> 11) << 2) + (i2 >> 7);
        size_t i = (size_t)bh * TT * DH + (size_t)(m & 2047) * DH + (i2 & 127);
        *(__half2*)&g_v16[i] = __floats2half2_rn(v0, v1);
    }
}

// ---------------- projection GEMM (R13: 8-warp + fp16 V branch) ----------------
__global__ __launch_bounds__(256, 2)
void gemm_proj(int dummy) {
    extern __shared__ uint16_t sm[];
    constexpr int STAGE = 4 * 4096;

    const int tid  = threadIdx.x;
    const int lane = tid & 31;
    const int warp = tid >> 5;
    const int wm   = warp >> 2;
    const int wn   = warp & 3;
    const int m0   = blockIdx.y * 128;
    const int n0   = blockIdx.x * 128;
    const int KT = KDIM / 32;

    float acc[4][4][4];
#pragma unroll
    for (int mi = 0; mi < 4; mi++)
#pragma unroll
        for (int ni = 0; ni < 4; ni++)
#pragma unroll
            for (int r = 0; r < 4; r++) acc[mi][ni][r] = 0.f;

    if (n0 >= 640) {
        const uint16_t* A = (const uint16_t*)g_x16;
        const uint16_t* B = (const uint16_t*)g_wv16;
        const int nv0 = n0 - 640;

#define LOAD_STAGE_V(kt, buf) do {                                              \
    int k0_ = (kt) * 32;                                                        \
    uint16_t* st_ = sm + (buf) * 8192;                                          \
    _Pragma("unroll")                                                           \
    for (int p = 0; p < 2; p++) {                                               \
        int id = tid + (p << 8);                                                \
        int row = id >> 2, c = id & 3;                                          \
        int so = SWZ(row, c);                                                   \
        cp16(st_ + so,        A + (size_t)(m0 + row) * KDIM + k0_ + (c << 3));  \
        cp16(st_ + 4096 + so, B + (size_t)(nv0 + row) * KDIM + k0_ + (c << 3)); \
    }                                                                           \
} while (0)

        LOAD_STAGE_V(0, 0); CP_COMMIT();
        LOAD_STAGE_V(1, 1); CP_COMMIT();

        int buf = 0;
        for (int kt = 0; kt < KT; kt++) {
            CP_WAIT(1);
            __syncthreads();
            if (kt + 2 < KT) {
                int nb = buf + 2; if (nb >= 3) nb -= 3;
                LOAD_STAGE_V(kt + 2, nb);
                CP_COMMIT();
            }

            const uint16_t* st = sm + buf * 8192;
            unsigned base_a = (unsigned)__cvta_generic_to_shared(st);
            unsigned base_b = base_a + 4096 * 2;

#pragma unroll
            for (int ks = 0; ks < 32; ks += 16) {
                unsigned Af[4][4], Bf[2][4];
                const int chk = (ks >> 3) + (lane >> 4);
#pragma unroll
                for (int mi = 0; mi < 4; mi++) {
                    int r = wm * 64 + mi * 16 + (lane & 15);
                    LDSM4(Af[mi], base_a + SWZ(r, chk) * 2);
                }
#pragma unroll
                for (int bi = 0; bi < 2; bi++) {
                    int r = wn * 32 + bi * 16 + (lane & 15);
                    LDSM4(Bf[bi], base_b + SWZ(r, chk) * 2);
                }
#pragma unroll
                for (int mi = 0; mi < 4; mi++)
#pragma unroll
                    for (int ni = 0; ni < 4; ni++)
                        MMA_F16(acc[mi][ni], Af[mi], Bf[ni >> 1][ni & 1], Bf[ni >> 1][(ni & 1) + 2]);
            }
            buf++; if (buf >= 3) buf = 0;
        }
#undef LOAD_STAGE_V
    } else {
        const uint16_t* Ah = (const uint16_t*)g_xhi;
        const uint16_t* Al = (const uint16_t*)g_xlo;
        const uint16_t* Bh = (const uint16_t*)g_whi;
        const uint16_t* Bl = (const uint16_t*)g_wlo;

#define LOAD_STAGE(kt, buf) do {                                                \
    int k0_ = (kt) * 32;                                                        \
    uint16_t* st_ = sm + (buf) * STAGE;                                         \
    _Pragma("unroll")                                                           \
    for (int p = 0; p < 2; p++) {                                               \
        int id = tid + (p << 8);                                                \
        int row = id >> 2, c = id & 3;                                          \
        int so = SWZ(row, c);                                                   \
        size_t ga = (size_t)(m0 + row) * KDIM + k0_ + (c << 3);                 \
        size_t gb = (size_t)(n0 + row) * KDIM + k0_ + (c << 3);                 \
        cp16(st_ + so,         Ah + ga);                                        \
        cp16(st_ + 4096 + so,  Al + ga);                                        \
        cp16(st_ + 8192 + so,  Bh + gb);                                        \
        cp16(st_ + 12288 + so, Bl + gb);                                        \
    }                                                                           \
} while (0)

        LOAD_STAGE(0, 0); CP_COMMIT();
        LOAD_STAGE(1, 1); CP_COMMIT();

        int buf = 0;
        for (int kt = 0; kt < KT; kt++) {
            CP_WAIT(1);
            __syncthreads();
            if (kt + 2 < KT) {
                int nb = buf + 2; if (nb >= 3) nb -= 3;
                LOAD_STAGE(kt + 2, nb);
                CP_COMMIT();
            }

            const uint16_t* st = sm + buf * STAGE;
            unsigned base_a  = (unsigned)__cvta_generic_to_shared(st);
            unsigned base_al = base_a + 4096 * 2;
            unsigned base_bh = base_a + 8192 * 2;
            unsigned base_bl = base_a + 12288 * 2;

#pragma unroll
            for (int ks = 0; ks < 32; ks += 16) {
                unsigned Af[4][4], Bhf[2][4], Blf[2][4];
                const int chk = (ks >> 3) + (lane >> 4);
#pragma unroll
                for (int mi = 0; mi < 4; mi++) {
                    int r = wm * 64 + mi * 16 + (lane & 15);
                    LDSM4(Af[mi], base_a + SWZ(r, chk) * 2);
                }
#pragma unroll
                for (int bi = 0; bi < 2; bi++) {
                    int r = wn * 32 + bi * 16 + (lane & 15);
                    LDSM4(Bhf[bi], base_bh + SWZ(r, chk) * 2);
                    LDSM4(Blf[bi], base_bl + SWZ(r, chk) * 2);
                }
#pragma unroll
                for (int mi = 0; mi < 4; mi++)
#pragma unroll
                    for (int ni = 0; ni < 4; ni++) {
                        MMA_BF16(acc[mi][ni], Af[mi], Bhf[ni >> 1][ni & 1], Bhf[ni >> 1][(ni & 1) + 2]);
                        MMA_BF16(acc[mi][ni], Af[mi], Blf[ni >> 1][ni & 1], Blf[ni >> 1][(ni & 1) + 2]);
                    }
#pragma unroll
                for (int mi = 0; mi < 4; mi++) {
                    int r = wm * 64 + mi * 16 + (lane & 15);
                    LDSM4(Af[mi], base_al + SWZ(r, chk) * 2);
                }
#pragma unroll
                for (int mi = 0; mi < 4; mi++)
#pragma unroll
                    for (int ni = 0; ni < 4; ni++)
                        MMA_BF16(acc[mi][ni], Af[mi], Bhf[ni >> 1][ni & 1], Bhf[ni >> 1][(ni & 1) + 2]);
            }
            buf++; if (buf >= 3) buf = 0;
        }
#undef LOAD_STAGE
    }

    // ---- shared epilogue ----
#pragma unroll
    for (int mi = 0; mi < 4; mi++)
#pragma unroll
        for (int ni = 0; ni < 4; ni++) {
            int mr = m0 + wm * 64 + mi * 16 + (lane >> 2);
            int nc = n0 + wn * 32 + ni * 8 + ((lane & 3) << 1);
            float* c = acc[mi][ni];
            float b0v = g_bred[nc], b1v = g_bred[nc + 1];
            proj_store(mr,     nc, c[0] + b0v, c[1] + b1v);
            proj_store(mr + 8, nc, c[2] + b0v, c[3] + b1v);
        }
}

// ---------------- fused flash attention (exact R8/R13 structure) ----------------
#define FL_STAGE 24576
#define FL_ELEMS (32768 + 3 * FL_STAGE)
#define FL_SMEM  (FL_ELEMS * 2)

__global__ __launch_bounds__(256)
void flash_attn(float* __restrict__ out) {
    extern __shared__ uint16_t fs[];
    const unsigned sb = (unsigned)__cvta_generic_to_shared(fs);

    const int tid  = threadIdx.x;
    const int lane = tid & 31;
    const int warp = tid >> 5;
    const int bh   = blockIdx.y;
    const int b    = bh >> 2;
    const int kvh  = bh & 3;
    const int q0   = blockIdx.x * 128;

    // ---- load Q (hi+lo) to smem ----
    {
        const uint16_t* qsrc0 = (const uint16_t*)g_qhi;
        const uint16_t* qsrc1 = (const uint16_t*)g_qlo;
#pragma unroll
        for (int p = 0; p < 16; p++) {
            int id = tid + (p << 8);
            int part = id >> 11, cid = id & 2047;
            int row = cid >> 4, c8 = cid & 15;
            unsigned dst = (unsigned)(part * 16384 + (c8 >> 2) * 4096 + SWZ(row, c8 & 3));
            const uint16_t* src = (part ? qsrc1 : qsrc0) + (size_t)(b * TT + q0 + row) * DH + c8 * 8;
            cp16s(sb + dst * 2, src);
        }
    }
    CP_COMMIT();

#define LOADKV(kt_, buf_) do {                                                   \
    const uint16_t* ksrc0 = (const uint16_t*)g_khi;                              \
    const uint16_t* ksrc1 = (const uint16_t*)g_klo;                              \
    const uint16_t* vsrc  = (const uint16_t*)g_v16;                              \
    unsigned stg = 32768u + (buf_) * (unsigned)FL_STAGE;                         \
    _Pragma("unroll")                                                            \
    for (int p = 0; p < 12; p++) {                                               \
        int id = tid + (p << 8);                                                 \
        int part = id >> 10, cid = id & 1023;                                    \
        int row = cid >> 4, c8 = cid & 15;                                       \
        unsigned dst = stg + part * 8192 + (c8 >> 2) * 2048 + SWZ(row, c8 & 3);  \
        const uint16_t* src = (part == 0 ? ksrc0 : (part == 1 ? ksrc1 : vsrc))   \
            + (size_t)bh * TT * DH + (size_t)((kt_) * 64 + row) * DH + c8 * 8;   \
        cp16s(sb + dst * 2, src);                                                \
    }                                                                            \
} while (0)

    LOADKV(0, 0); CP_COMMIT();
    LOADKV(1, 1); CP_COMMIT();

    float m0s = -1e30f, m1s = -1e30f, l0s = 0.f, l1s = 0.f;
    float O[16][4];
#pragma unroll
    for (int i = 0; i < 16; i++)
#pragma unroll
        for (int j = 0; j < 4; j++) O[i][j] = 0.f;

    const int NT = TT / 64;   // 32 tiles
    int buf = 0;
    for (int kt = 0; kt < NT; kt++) {
        CP_WAIT(1);
        __syncthreads();
        if (kt + 2 < NT) {
            int nb = buf + 2; if (nb >= 3) nb -= 3;
            LOADKV(kt + 2, nb);
            CP_COMMIT();
        }

        const unsigned stgK = sb + (32768u + buf * (unsigned)FL_STAGE) * 2;
        const unsigned stgV = stgK + 16384u * 2;

        // ---- scores: sacc[8][4] = Q . K^T over d=128 ----
        float sacc[8][4];
#pragma unroll
        for (int i = 0; i < 8; i++)
#pragma unroll
            for (int j = 0; j < 4; j++) sacc[i][j] = 0.f;

#pragma unroll
        for (int ks = 0; ks < 8; ks++) {
            const int kc = ks >> 1;
            const int c  = ((ks & 1) << 1) + (lane >> 4);
            unsigned ah[4], al[4], kh[4][4], kl[4][4];
            LDSM4(ah, sb + (0     + kc * 4096 + SWZ(warp * 16 + (lane & 15), c)) * 2);
            LDSM4(al, sb + (16384 + kc * 4096 + SWZ(warp * 16 + (lane & 15), c)) * 2);
#pragma unroll
            for (int nt = 0; nt < 4; nt++) {
                LDSM4(kh[nt], stgK + (kc * 2048 + SWZ(nt * 16 + (lane & 15), c)) * 2);
                LDSM4(kl[nt], stgK + (8192 + kc * 2048 + SWZ(nt * 16 + (lane & 15), c)) * 2);
            }
#pragma unroll
            for (int nt = 0; nt < 4; nt++)
#pragma unroll
                for (int sub = 0; sub < 2; sub++) {
                    int ni = nt * 2 + sub;
                    MMA_BF16(sacc[ni], ah, kh[nt][sub], kh[nt][sub + 2]);
                    MMA_BF16(sacc[ni], al, kh[nt][sub], kh[nt][sub + 2]);
                    MMA_BF16(sacc[ni], ah, kl[nt][sub], kl[nt][sub + 2]);
                }
        }

        // ---- online softmax ----
        float tm0 = -1e30f, tm1 = -1e30f;
#pragma unroll
        for (int ni = 0; ni < 8; ni++) {
            tm0 = fmaxf(tm0, fmaxf(sacc[ni][0], sacc[ni][1]));
            tm1 = fmaxf(tm1, fmaxf(sacc[ni][2], sacc[ni][3]));
        }
        tm0 = fmaxf(tm0, __shfl_xor_sync(~0u, tm0, 1));
        tm0 = fmaxf(tm0, __shfl_xor_sync(~0u, tm0, 2));
        tm1 = fmaxf(tm1, __shfl_xor_sync(~0u, tm1, 1));
        tm1 = fmaxf(tm1, __shfl_xor_sync(~0u, tm1, 2));

        float mn0 = fmaxf(m0s, tm0), mn1 = fmaxf(m1s, tm1);
        float al0 = __expf(m0s - mn0), al1 = __expf(m1s - mn1);
        m0s = mn0; m1s = mn1;

        float rs0 = 0.f, rs1 = 0.f;
#pragma unroll
        for (int ni = 0; ni < 8; ni++) {
            sacc[ni][0] = __expf(sacc[ni][0] - mn0);
            sacc[ni][1] = __expf(sacc[ni][1] - mn0);
            sacc[ni][2] = __expf(sacc[ni][2] - mn1);
            sacc[ni][3] = __expf(sacc[ni][3] - mn1);
            rs0 += sacc[ni][0] + sacc[ni][1];
            rs1 += sacc[ni][2] + sacc[ni][3];
        }
        rs0 += __shfl_xor_sync(~0u, rs0, 1);
        rs0 += __shfl_xor_sync(~0u, rs0, 2);
        rs1 += __shfl_xor_sync(~0u, rs1, 1);
        rs1 += __shfl_xor_sync(~0u, rs1, 2);
        l0s = l0s * al0 + rs0;
        l1s = l1s * al1 + rs1;

#pragma unroll
        for (int dj = 0; dj < 16; dj++) {
            O[dj][0] *= al0; O[dj][1] *= al0;
            O[dj][2] *= al1; O[dj][3] *= al1;
        }

        // ---- PV: O += P(fp16 regs) x V (trans-ldmatrix from [t][d]) ----
#pragma unroll
        for (int kt2 = 0; kt2 < 4; kt2++) {
            unsigned pa[4];
            pa[0] = h2u(__floats2half2_rn(sacc[kt2 * 2][0],     sacc[kt2 * 2][1]));
            pa[1] = h2u(__floats2half2_rn(sacc[kt2 * 2][2],     sacc[kt2 * 2][3]));
            pa[2] = h2u(__floats2half2_rn(sacc[kt2 * 2 + 1][0], sacc[kt2 * 2 + 1][1]));
            pa[3] = h2u(__floats2half2_rn(sacc[kt2 * 2 + 1][2], sacc[kt2 * 2 + 1][3]));
#pragma unroll
            for (int dt = 0; dt < 8; dt++) {
                unsigned v[4];
                const int chunk = dt >> 1;
                const int c = ((dt & 1) << 1) + (lane >> 4);
                LDSM4T(v, stgV + (chunk * 2048 + SWZ(kt2 * 16 + (lane & 15), c)) * 2);
                MMA_F16(O[dt * 2],     pa, v[0], v[1]);
                MMA_F16(O[dt * 2 + 1], pa, v[2], v[3]);
            }
        }

        buf++; if (buf >= 3) buf = 0;
    }
#undef LOADKV

    // ---- epilogue ----
    float inv0 = 1.f / l0s, inv1 = 1.f / l1s;
    int r = warp * 16 + (lane >> 2);
    float* o0 = out + (size_t)(b * TT + q0 + r) * 512 + kvh * 128;
    float* o1 = o0 + 8 * 512;
#pragma unroll
    for (int dj = 0; dj < 16; dj++) {
        int d = dj * 8 + ((lane & 3) << 1);
        *(float2*)(o0 + d) = make_float2(O[dj][0] * inv0, O[dj][1] * inv0);
        *(float2*)(o1 + d) = make_float2(O[dj][2] * inv1, O[dj][3] * inv1);
    }
}

// ---------------- launch ----------------
extern "C" void kernel_launch(void* const* d_in, const int* in_sizes, int n_in,
                              void* d_out, int out_size) {
    (void)in_sizes; (void)n_in; (void)out_size;
    const float* x = (const float*)d_in[0];
    const float* W = (const float*)d_in[1];
    const float* b = (const float*)d_in[2];
    float* out = (float*)d_out;

    const int SMEM_AB = 3 * 4 * 4096 * 2;   // 96KB
    cudaFuncSetAttribute(gemm_proj, cudaFuncAttributeMaxDynamicSharedMemorySize, SMEM_AB);
    cudaFuncSetAttribute(flash_attn, cudaFuncAttributeMaxDynamicSharedMemorySize, FL_SMEM);

    prep_xw<<<8192 + 9216, 256>>>(x, W, b);
    gemm_proj<<<dim3(9, 64), 256, SMEM_AB>>>(0);
    flash_attn<<<dim3(16, 16), 256, FL_SMEM>>>(out);
}

// round 17
// speedup vs baseline: 1.1443x; 1.0003x over previous
#include <cuda_runtime.h>
#include <cuda_bf16.h>
#include <cuda_fp16.h>
#include <cstdint>
#include <math.h>

typedef __nv_bfloat16 bf16;

#define TT    2048
#define KDIM  2048
#define DH    128
#define NREDC 1152
#define MROWS 8192
#define NBH   16
#define SCALE 0.08838834764831845f   // 1/sqrt(128)

// ---------------- device scratch ----------------
__device__ bf16   g_xhi[(size_t)MROWS*KDIM];
__device__ bf16   g_xlo[(size_t)MROWS*KDIM];
__device__ __half g_x16[(size_t)MROWS*KDIM];     // x single fp16 (V-GEMM)
__device__ bf16   g_whi[(size_t)NREDC*KDIM];     // only rows < 640 used
__device__ bf16   g_wlo[(size_t)NREDC*KDIM];
__device__ __half g_wv16[(size_t)512*KDIM];      // V weights fp16 (rows n-640)
__device__ float  g_bred[NREDC];
__device__ bf16   g_qhi[(size_t)MROWS*DH];
__device__ bf16   g_qlo[(size_t)MROWS*DH];
__device__ bf16   g_khi[(size_t)NBH*TT*DH];
__device__ bf16   g_klo[(size_t)NBH*TT*DH];
__device__ __half g_v16[(size_t)NBH*TT*DH];      // V [bh][t][d], single fp16

// ---------------- helpers ----------------
__device__ __forceinline__ void split2(float v, bf16& h, bf16& l) {
    h = __float2bfloat16(v);
    l = __float2bfloat16(v - __bfloat162float(h));
}
__device__ __forceinline__ unsigned h2u(__half2 h) {
    return *reinterpret_cast<unsigned*>(&h);
}
__device__ __forceinline__ unsigned b2u(__nv_bfloat162 h) {
    return *reinterpret_cast<unsigned*>(&h);
}
__device__ __forceinline__ void cp16(void* sp, const void* gp) {
    unsigned s = (unsigned)__cvta_generic_to_shared(sp);
    asm volatile("cp.async.cg.shared.global [%0], [%1], 16;\n" :: "r"(s), "l"(gp));
}
__device__ __forceinline__ void cp16s(unsigned s, const void* gp) {
    asm volatile("cp.async.cg.shared.global [%0], [%1], 16;\n" :: "r"(s), "l"(gp));
}
#define CP_COMMIT() asm volatile("cp.async.commit_group;\n")
#define CP_WAIT(n)  asm volatile("cp.async.wait_group %0;\n" :: "n"(n))

// swizzled element offset inside an Nx32 16-bit tile (64B rows, 16B chunks)
#define SWZ(r, c) (((r) << 5) + ((((c) ^ (((r) >> 1) & 3))) << 3))

#define LDSM4(R, addr) \
    asm volatile("ldmatrix.sync.aligned.m8n8.x4.shared.b16 {%0,%1,%2,%3}, [%4];" \
        : "=r"((R)[0]), "=r"((R)[1]), "=r"((R)[2]), "=r"((R)[3]) : "r"(addr))

#define LDSM4T(R, addr) \
    asm volatile("ldmatrix.sync.aligned.m8n8.x4.trans.shared.b16 {%0,%1,%2,%3}, [%4];" \
        : "=r"((R)[0]), "=r"((R)[1]), "=r"((R)[2]), "=r"((R)[3]) : "r"(addr))

#define MMA_BF16(C, A, b0, b1) \
    asm volatile("mma.sync.aligned.m16n8k16.row.col.f32.bf16.bf16.f32 " \
        "{%0,%1,%2,%3},{%4,%5,%6,%7},{%8,%9},{%0,%1,%2,%3};" \
        : "+f"((C)[0]), "+f"((C)[1]), "+f"((C)[2]), "+f"((C)[3]) \
        : "r"((A)[0]), "r"((A)[1]), "r"((A)[2]), "r"((A)[3]), "r"(b0), "r"(b1))

#define MMA_F16(C, A, b0, b1) \
    asm volatile("mma.sync.aligned.m16n8k16.row.col.f32.f16.f16.f32 " \
        "{%0,%1,%2,%3},{%4,%5,%6,%7},{%8,%9},{%0,%1,%2,%3};" \
        : "+f"((C)[0]), "+f"((C)[1]), "+f"((C)[2]), "+f"((C)[3]) \
        : "r"((A)[0]), "r"((A)[1]), "r"((A)[2]), "r"((A)[3]), "r"(b0), "r"(b1))

// ---------------- merged prep: blocks [0,8192) = x, [8192,9344) = w ----------------
// Both branches: 8 consecutive elements/thread, 16B vector stores.
__global__ void prep_xw(const float* __restrict__ x,
                        const float* __restrict__ W,
                        const float* __restrict__ b) {
    if (blockIdx.x < 8192) {
        size_t i = ((size_t)blockIdx.x * 256 + threadIdx.x) * 8;
        float4 a0 = *(const float4*)(x + i);
        float4 a1 = *(const float4*)(x + i + 4);
        float arr[8] = {a0.x, a0.y, a0.z, a0.w, a1.x, a1.y, a1.z, a1.w};
        bf16 hh[8], ll[8];
        unsigned hx[4];
#pragma unroll
        for (int j = 0; j < 8; j++) split2(arr[j], hh[j], ll[j]);
#pragma unroll
        for (int j = 0; j < 4; j++)
            hx[j] = h2u(__floats2half2_rn(arr[j * 2], arr[j * 2 + 1]));
        uint4 vh, vl;
        vh.x = b2u(__halves2bfloat162(hh[0], hh[1]));
        vh.y = b2u(__halves2bfloat162(hh[2], hh[3]));
        vh.z = b2u(__halves2bfloat162(hh[4], hh[5]));
        vh.w = b2u(__halves2bfloat162(hh[6], hh[7]));
        vl.x = b2u(__halves2bfloat162(ll[0], ll[1]));
        vl.y = b2u(__halves2bfloat162(ll[2], ll[3]));
        vl.z = b2u(__halves2bfloat162(ll[4], ll[5]));
        vl.w = b2u(__halves2bfloat162(ll[6], ll[7]));
        *(uint4*)&g_xhi[i] = vh;
        *(uint4*)&g_xlo[i] = vl;
        *(uint4*)&g_x16[i] = make_uint4(hx[0], hx[1], hx[2], hx[3]);
    } else {
        int t2 = (blockIdx.x - 8192) * 256 + threadIdx.x;   // < 294912
        size_t e = (size_t)t2 * 8;
        int n = (int)(e >> 11), c = (int)(e & 2047);        // c multiple of 8
        float v[8];
        if (n < 128) {
#pragma unroll
            for (int j = 0; j < 8; j++) v[j] = 0.f;
#pragma unroll
            for (int h = 0; h < 16; h++) {
                const float* wr = W + (size_t)(h * 128 + n) * KDIM + c;
                float4 w0 = *(const float4*)wr;
                float4 w1 = *(const float4*)(wr + 4);
                v[0] += w0.x; v[1] += w0.y; v[2] += w0.z; v[3] += w0.w;
                v[4] += w1.x; v[5] += w1.y; v[6] += w1.z; v[7] += w1.w;
            }
#pragma unroll
            for (int j = 0; j < 8; j++) v[j] *= SCALE;
        } else {
            const float* wr = W + (size_t)(n + 1920) * KDIM + c;
            float4 w0 = *(const float4*)wr;
            float4 w1 = *(const float4*)(wr + 4);
            v[0] = w0.x; v[1] = w0.y; v[2] = w0.z; v[3] = w0.w;
            v[4] = w1.x; v[5] = w1.y; v[6] = w1.z; v[7] = w1.w;
        }

        if (n < 640) {
            bf16 hh[8], ll[8];
#pragma unroll
            for (int j = 0; j < 8; j++) split2(v[j], hh[j], ll[j]);
            uint4 vh, vl;
            vh.x = b2u(__halves2bfloat162(hh[0], hh[1]));
            vh.y = b2u(__halves2bfloat162(hh[2], hh[3]));
            vh.z = b2u(__halves2bfloat162(hh[4], hh[5]));
            vh.w = b2u(__halves2bfloat162(hh[6], hh[7]));
            vl.x = b2u(__halves2bfloat162(ll[0], ll[1]));
            vl.y = b2u(__halves2bfloat162(ll[2], ll[3]));
            vl.z = b2u(__halves2bfloat162(ll[4], ll[5]));
            vl.w = b2u(__halves2bfloat162(ll[6], ll[7]));
            *(uint4*)&g_whi[e] = vh;
            *(uint4*)&g_wlo[e] = vl;
        } else {
            uint4 hv;
            hv.x = h2u(__floats2half2_rn(v[0], v[1]));
            hv.y = h2u(__floats2half2_rn(v[2], v[3]));
            hv.z = h2u(__floats2half2_rn(v[4], v[5]));
            hv.w = h2u(__floats2half2_rn(v[6], v[7]));
            *(uint4*)&g_wv16[e - (size_t)640 * KDIM] = hv;
        }

        if (t2 < NREDC) {
            float bv;
            if (t2 < 128) {
                bv = 0.f;
#pragma unroll
                for (int h = 0; h < 16; h++) bv += b[h * 128 + t2];
                bv *= SCALE;
            } else bv = b[t2 + 1920];
            g_bred[t2] = bv;
        }
    }
}

// ---------------- projection epilogue scatter ----------------
__device__ __forceinline__ void proj_store(int m, int n, float v0, float v1) {
    if (n < 128) {
        bf16 h0, l0, h1, l1;
        split2(v0, h0, l0);  split2(v1, h1, l1);
        size_t i = (size_t)m * DH + n;
        *(__nv_bfloat162*)&g_qhi[i] = __halves2bfloat162(h0, h1);
        *(__nv_bfloat162*)&g_qlo[i] = __halves2bfloat162(l0, l1);
    } else if (n < 640) {
        bf16 h0, l0, h1, l1;
        split2(v0, h0, l0);  split2(v1, h1, l1);
        int i2 = n - 128;
        int bh = ((m >> 11) << 2) + (i2 >> 7);
        size_t i = (size_t)bh * TT * DH + (size_t)(m & 2047) * DH + (i2 & 127);
        *(__nv_bfloat162*)&g_khi[i] = __halves2bfloat162(h0, h1);
        *(__nv_bfloat162*)&g_klo[i] = __halves2bfloat162(l0, l1);
    } else {
        int i2 = n - 640;
        int bh = ((m >> 11) << 2) + (i2 >> 7);
        size_t i = (size_t)bh * TT * DH + (size_t)(m & 2047) * DH + (i2 & 127);
        *(__half2*)&g_v16[i] = __floats2half2_rn(v0, v1);
    }
}

// ---------------- projection GEMM (R13: 8-warp + fp16 V branch) ----------------
__global__ __launch_bounds__(256, 2)
void gemm_proj(int dummy) {
    extern __shared__ uint16_t sm[];
    constexpr int STAGE = 4 * 4096;

    const int tid  = threadIdx.x;
    const int lane = tid & 31;
    const int warp = tid >> 5;
    const int wm   = warp >> 2;
    const int wn   = warp & 3;
    const int m0   = blockIdx.y * 128;
    const int n0   = blockIdx.x * 128;
    const int KT = KDIM / 32;

    float acc[4][4][4];
#pragma unroll
    for (int mi = 0; mi < 4; mi++)
#pragma unroll
        for (int ni = 0; ni < 4; ni++)
#pragma unroll
            for (int r = 0; r < 4; r++) acc[mi][ni][r] = 0.f;

    if (n0 >= 640) {
        const uint16_t* A = (const uint16_t*)g_x16;
        const uint16_t* B = (const uint16_t*)g_wv16;
        const int nv0 = n0 - 640;

#define LOAD_STAGE_V(kt, buf) do {                                              \
    int k0_ = (kt) * 32;                                                        \
    uint16_t* st_ = sm + (buf) * 8192;                                          \
    _Pragma("unroll")                                                           \
    for (int p = 0; p < 2; p++) {                                               \
        int id = tid + (p << 8);                                                \
        int row = id >> 2, c = id & 3;                                          \
        int so = SWZ(row, c);                                                   \
        cp16(st_ + so,        A + (size_t)(m0 + row) * KDIM + k0_ + (c << 3));  \
        cp16(st_ + 4096 + so, B + (size_t)(nv0 + row) * KDIM + k0_ + (c << 3)); \
    }                                                                           \
} while (0)

        LOAD_STAGE_V(0, 0); CP_COMMIT();
        LOAD_STAGE_V(1, 1); CP_COMMIT();

        int buf = 0;
        for (int kt = 0; kt < KT; kt++) {
            CP_WAIT(1);
            __syncthreads();
            if (kt + 2 < KT) {
                int nb = buf + 2; if (nb >= 3) nb -= 3;
                LOAD_STAGE_V(kt + 2, nb);
                CP_COMMIT();
            }

            const uint16_t* st = sm + buf * 8192;
            unsigned base_a = (unsigned)__cvta_generic_to_shared(st);
            unsigned base_b = base_a + 4096 * 2;

#pragma unroll
            for (int ks = 0; ks < 32; ks += 16) {
                unsigned Af[4][4], Bf[2][4];
                const int chk = (ks >> 3) + (lane >> 4);
#pragma unroll
                for (int mi = 0; mi < 4; mi++) {
                    int r = wm * 64 + mi * 16 + (lane & 15);
                    LDSM4(Af[mi], base_a + SWZ(r, chk) * 2);
                }
#pragma unroll
                for (int bi = 0; bi < 2; bi++) {
                    int r = wn * 32 + bi * 16 + (lane & 15);
                    LDSM4(Bf[bi], base_b + SWZ(r, chk) * 2);
                }
#pragma unroll
                for (int mi = 0; mi < 4; mi++)
#pragma unroll
                    for (int ni = 0; ni < 4; ni++)
                        MMA_F16(acc[mi][ni], Af[mi], Bf[ni >> 1][ni & 1], Bf[ni >> 1][(ni & 1) + 2]);
            }
            buf++; if (buf >= 3) buf = 0;
        }
#undef LOAD_STAGE_V
    } else {
        const uint16_t* Ah = (const uint16_t*)g_xhi;
        const uint16_t* Al = (const uint16_t*)g_xlo;
        const uint16_t* Bh = (const uint16_t*)g_whi;
        const uint16_t* Bl = (const uint16_t*)g_wlo;

#define LOAD_STAGE(kt, buf) do {                                                \
    int k0_ = (kt) * 32;                                                        \
    uint16_t* st_ = sm + (buf) * STAGE;                                         \
    _Pragma("unroll")                                                           \
    for (int p = 0; p < 2; p++) {                                               \
        int id = tid + (p << 8);                                                \
        int row = id >> 2, c = id & 3;                                          \
        int so = SWZ(row, c);                                                   \
        size_t ga = (size_t)(m0 + row) * KDIM + k0_ + (c << 3);                 \
        size_t gb = (size_t)(n0 + row) * KDIM + k0_ + (c << 3);                 \
        cp16(st_ + so,         Ah + ga);                                        \
        cp16(st_ + 4096 + so,  Al + ga);                                        \
        cp16(st_ + 8192 + so,  Bh + gb);                                        \
        cp16(st_ + 12288 + so, Bl + gb);                                        \
    }                                                                           \
} while (0)

        LOAD_STAGE(0, 0); CP_COMMIT();
        LOAD_STAGE(1, 1); CP_COMMIT();

        int buf = 0;
        for (int kt = 0; kt < KT; kt++) {
            CP_WAIT(1);
            __syncthreads();
            if (kt + 2 < KT) {
                int nb = buf + 2; if (nb >= 3) nb -= 3;
                LOAD_STAGE(kt + 2, nb);
                CP_COMMIT();
            }

            const uint16_t* st = sm + buf * STAGE;
            unsigned base_a  = (unsigned)__cvta_generic_to_shared(st);
            unsigned base_al = base_a + 4096 * 2;
            unsigned base_bh = base_a + 8192 * 2;
            unsigned base_bl = base_a + 12288 * 2;

#pragma unroll
            for (int ks = 0; ks < 32; ks += 16) {
                unsigned Af[4][4], Bhf[2][4], Blf[2][4];
                const int chk = (ks >> 3) + (lane >> 4);
#pragma unroll
                for (int mi = 0; mi < 4; mi++) {
                    int r = wm * 64 + mi * 16 + (lane & 15);
                    LDSM4(Af[mi], base_a + SWZ(r, chk) * 2);
                }
#pragma unroll
                for (int bi = 0; bi < 2; bi++) {
                    int r = wn * 32 + bi * 16 + (lane & 15);
                    LDSM4(Bhf[bi], base_bh + SWZ(r, chk) * 2);
                    LDSM4(Blf[bi], base_bl + SWZ(r, chk) * 2);
                }
#pragma unroll
                for (int mi = 0; mi < 4; mi++)
#pragma unroll
                    for (int ni = 0; ni < 4; ni++) {
                        MMA_BF16(acc[mi][ni], Af[mi], Bhf[ni >> 1][ni & 1], Bhf[ni >> 1][(ni & 1) + 2]);
                        MMA_BF16(acc[mi][ni], Af[mi], Blf[ni >> 1][ni & 1], Blf[ni >> 1][(ni & 1) + 2]);
                    }
#pragma unroll
                for (int mi = 0; mi < 4; mi++) {
                    int r = wm * 64 + mi * 16 + (lane & 15);
                    LDSM4(Af[mi], base_al + SWZ(r, chk) * 2);
                }
#pragma unroll
                for (int mi = 0; mi < 4; mi++)
#pragma unroll
                    for (int ni = 0; ni < 4; ni++)
                        MMA_BF16(acc[mi][ni], Af[mi], Bhf[ni >> 1][ni & 1], Bhf[ni >> 1][(ni & 1) + 2]);
            }
            buf++; if (buf >= 3) buf = 0;
        }
#undef LOAD_STAGE
    }

    // ---- shared epilogue ----
#pragma unroll
    for (int mi = 0; mi < 4; mi++)
#pragma unroll
        for (int ni = 0; ni < 4; ni++) {
            int mr = m0 + wm * 64 + mi * 16 + (lane >> 2);
            int nc = n0 + wn * 32 + ni * 8 + ((lane & 3) << 1);
            float* c = acc[mi][ni];
            float b0v = g_bred[nc], b1v = g_bred[nc + 1];
            proj_store(mr,     nc, c[0] + b0v, c[1] + b1v);
            proj_store(mr + 8, nc, c[2] + b0v, c[3] + b1v);
        }
}

// ---------------- fused flash attention (exact R8/R13 structure) ----------------
#define FL_STAGE 24576
#define FL_ELEMS (32768 + 3 * FL_STAGE)
#define FL_SMEM  (FL_ELEMS * 2)

__global__ __launch_bounds__(256)
void flash_attn(float* __restrict__ out) {
    extern __shared__ uint16_t fs[];
    const unsigned sb = (unsigned)__cvta_generic_to_shared(fs);

    const int tid  = threadIdx.x;
    const int lane = tid & 31;
    const int warp = tid >> 5;
    const int bh   = blockIdx.y;
    const int b    = bh >> 2;
    const int kvh  = bh & 3;
    const int q0   = blockIdx.x * 128;

    // ---- load Q (hi+lo) to smem ----
    {
        const uint16_t* qsrc0 = (const uint16_t*)g_qhi;
        const uint16_t* qsrc1 = (const uint16_t*)g_qlo;
#pragma unroll
        for (int p = 0; p < 16; p++) {
            int id = tid + (p << 8);
            int part = id >> 11, cid = id & 2047;
            int row = cid >> 4, c8 = cid & 15;
            unsigned dst = (unsigned)(part * 16384 + (c8 >> 2) * 4096 + SWZ(row, c8 & 3));
            const uint16_t* src = (part ? qsrc1 : qsrc0) + (size_t)(b * TT + q0 + row) * DH + c8 * 8;
            cp16s(sb + dst * 2, src);
        }
    }
    CP_COMMIT();

#define LOADKV(kt_, buf_) do {                                                   \
    const uint16_t* ksrc0 = (const uint16_t*)g_khi;                              \
    const uint16_t* ksrc1 = (const uint16_t*)g_klo;                              \
    const uint16_t* vsrc  = (const uint16_t*)g_v16;                              \
    unsigned stg = 32768u + (buf_) * (unsigned)FL_STAGE;                         \
    _Pragma("unroll")                                                            \
    for (int p = 0; p < 12; p++) {                                               \
        int id = tid + (p << 8);                                                 \
        int part = id >> 10, cid = id & 1023;                                    \
        int row = cid >> 4, c8 = cid & 15;                                       \
        unsigned dst = stg + part * 8192 + (c8 >> 2) * 2048 + SWZ(row, c8 & 3);  \
        const uint16_t* src = (part == 0 ? ksrc0 : (part == 1 ? ksrc1 : vsrc))   \
            + (size_t)bh * TT * DH + (size_t)((kt_) * 64 + row) * DH + c8 * 8;   \
        cp16s(sb + dst * 2, src);                                                \
    }                                                                            \
} while (0)

    LOADKV(0, 0); CP_COMMIT();
    LOADKV(1, 1); CP_COMMIT();

    float m0s = -1e30f, m1s = -1e30f, l0s = 0.f, l1s = 0.f;
    float O[16][4];
#pragma unroll
    for (int i = 0; i < 16; i++)
#pragma unroll
        for (int j = 0; j < 4; j++) O[i][j] = 0.f;

    const int NT = TT / 64;   // 32 tiles
    int buf = 0;
    for (int kt = 0; kt < NT; kt++) {
        CP_WAIT(1);
        __syncthreads();
        if (kt + 2 < NT) {
            int nb = buf + 2; if (nb >= 3) nb -= 3;
            LOADKV(kt + 2, nb);
            CP_COMMIT();
        }

        const unsigned stgK = sb + (32768u + buf * (unsigned)FL_STAGE) * 2;
        const unsigned stgV = stgK + 16384u * 2;

        // ---- scores: sacc[8][4] = Q . K^T over d=128 ----
        float sacc[8][4];
#pragma unroll
        for (int i = 0; i < 8; i++)
#pragma unroll
            for (int j = 0; j < 4; j++) sacc[i][j] = 0.f;

#pragma unroll
        for (int ks = 0; ks < 8; ks++) {
            const int kc = ks >> 1;
            const int c  = ((ks & 1) << 1) + (lane >> 4);
            unsigned ah[4], al[4], kh[4][4], kl[4][4];
            LDSM4(ah, sb + (0     + kc * 4096 + SWZ(warp * 16 + (lane & 15), c)) * 2);
            LDSM4(al, sb + (16384 + kc * 4096 + SWZ(warp * 16 + (lane & 15), c)) * 2);
#pragma unroll
            for (int nt = 0; nt < 4; nt++) {
                LDSM4(kh[nt], stgK + (kc * 2048 + SWZ(nt * 16 + (lane & 15), c)) * 2);
                LDSM4(kl[nt], stgK + (8192 + kc * 2048 + SWZ(nt * 16 + (lane & 15), c)) * 2);
            }
#pragma unroll
            for (int nt = 0; nt < 4; nt++)
#pragma unroll
                for (int sub = 0; sub < 2; sub++) {
                    int ni = nt * 2 + sub;
                    MMA_BF16(sacc[ni], ah, kh[nt][sub], kh[nt][sub + 2]);
                    MMA_BF16(sacc[ni], al, kh[nt][sub], kh[nt][sub + 2]);
                    MMA_BF16(sacc[ni], ah, kl[nt][sub], kl[nt][sub + 2]);
                }
        }

        // ---- online softmax ----
        float tm0 = -1e30f, tm1 = -1e30f;
#pragma unroll
        for (int ni = 0; ni < 8; ni++) {
            tm0 = fmaxf(tm0, fmaxf(sacc[ni][0], sacc[ni][1]));
            tm1 = fmaxf(tm1, fmaxf(sacc[ni][2], sacc[ni][3]));
        }
        tm0 = fmaxf(tm0, __shfl_xor_sync(~0u, tm0, 1));
        tm0 = fmaxf(tm0, __shfl_xor_sync(~0u, tm0, 2));
        tm1 = fmaxf(tm1, __shfl_xor_sync(~0u, tm1, 1));
        tm1 = fmaxf(tm1, __shfl_xor_sync(~0u, tm1, 2));

        float mn0 = fmaxf(m0s, tm0), mn1 = fmaxf(m1s, tm1);
        float al0 = __expf(m0s - mn0), al1 = __expf(m1s - mn1);
        m0s = mn0; m1s = mn1;

        float rs0 = 0.f, rs1 = 0.f;
#pragma unroll
        for (int ni = 0; ni < 8; ni++) {
            sacc[ni][0] = __expf(sacc[ni][0] - mn0);
            sacc[ni][1] = __expf(sacc[ni][1] - mn0);
            sacc[ni][2] = __expf(sacc[ni][2] - mn1);
            sacc[ni][3] = __expf(sacc[ni][3] - mn1);
            rs0 += sacc[ni][0] + sacc[ni][1];
            rs1 += sacc[ni][2] + sacc[ni][3];
        }
        rs0 += __shfl_xor_sync(~0u, rs0, 1);
        rs0 += __shfl_xor_sync(~0u, rs0, 2);
        rs1 += __shfl_xor_sync(~0u, rs1, 1);
        rs1 += __shfl_xor_sync(~0u, rs1, 2);
        l0s = l0s * al0 + rs0;
        l1s = l1s * al1 + rs1;

#pragma unroll
        for (int dj = 0; dj < 16; dj++) {
            O[dj][0] *= al0; O[dj][1] *= al0;
            O[dj][2] *= al1; O[dj][3] *= al1;
        }

        // ---- PV: O += P(fp16 regs) x V (trans-ldmatrix from [t][d]) ----
#pragma unroll
        for (int kt2 = 0; kt2 < 4; kt2++) {
            unsigned pa[4];
            pa[0] = h2u(__floats2half2_rn(sacc[kt2 * 2][0],     sacc[kt2 * 2][1]));
            pa[1] = h2u(__floats2half2_rn(sacc[kt2 * 2][2],     sacc[kt2 * 2][3]));
            pa[2] = h2u(__floats2half2_rn(sacc[kt2 * 2 + 1][0], sacc[kt2 * 2 + 1][1]));
            pa[3] = h2u(__floats2half2_rn(sacc[kt2 * 2 + 1][2], sacc[kt2 * 2 + 1][3]));
#pragma unroll
            for (int dt = 0; dt < 8; dt++) {
                unsigned v[4];
                const int chunk = dt >> 1;
                const int c = ((dt & 1) << 1) + (lane >> 4);
                LDSM4T(v, stgV + (chunk * 2048 + SWZ(kt2 * 16 + (lane & 15), c)) * 2);
                MMA_F16(O[dt * 2],     pa, v[0], v[1]);
                MMA_F16(O[dt * 2 + 1], pa, v[2], v[3]);
            }
        }

        buf++; if (buf >= 3) buf = 0;
    }
#undef LOADKV

    // ---- epilogue ----
    float inv0 = 1.f / l0s, inv1 = 1.f / l1s;
    int r = warp * 16 + (lane >> 2);
    float* o0 = out + (size_t)(b * TT + q0 + r) * 512 + kvh * 128;
    float* o1 = o0 + 8 * 512;
#pragma unroll
    for (int dj = 0; dj < 16; dj++) {
        int d = dj * 8 + ((lane & 3) << 1);
        *(float2*)(o0 + d) = make_float2(O[dj][0] * inv0, O[dj][1] * inv0);
        *(float2*)(o1 + d) = make_float2(O[dj][2] * inv1, O[dj][3] * inv1);
    }
}

// ---------------- launch ----------------
extern "C" void kernel_launch(void* const* d_in, const int* in_sizes, int n_in,
                              void* d_out, int out_size) {
    (void)in_sizes; (void)n_in; (void)out_size;
    const float* x = (const float*)d_in[0];
    const float* W = (const float*)d_in[1];
    const float* b = (const float*)d_in[2];
    float* out = (float*)d_out;

    const int SMEM_AB = 3 * 4 * 4096 * 2;   // 96KB
    cudaFuncSetAttribute(gemm_proj, cudaFuncAttributeMaxDynamicSharedMemorySize, SMEM_AB);
    cudaFuncSetAttribute(flash_attn, cudaFuncAttributeMaxDynamicSharedMemorySize, FL_SMEM);

    prep_xw<<<8192 + 1152, 256>>>(x, W, b);
    gemm_proj<<<dim3(9, 64), 256, SMEM_AB>>>(0);
    flash_attn<<<dim3(16, 16), 256, FL_SMEM>>>(out);
}